// round 2
// baseline (speedup 1.0000x reference)
#include <cuda_runtime.h>
#include <cstdint>
#include <math.h>

// ---------------- problem constants (fixed by reference_code) ----------------
#define BB   8
#define LQ   300
#define DM   256
#define NH   8
#define HD   32
#define NL   4
#define NP   4
#define DFF  1024
#define LV   20197
#define NQ   (BB*LQ)          // 2400
#define MV   (BB*LV)          // 161576

// level constants
__device__ __constant__ int   c_H[NL]  = {100, 50, 25, 13};
__device__ __constant__ int   c_W[NL]  = {152, 76, 38, 19};
__device__ __constant__ int   c_S0[NL] = {0, 15200, 19000, 19950};

// ---------------- scratch (device globals; no allocations allowed) ----------
__device__ float g_qk   [NQ*DM];
__device__ float g_qkv  [NQ*3*DM];
__device__ float g_scores[(size_t)BB*NH*LQ*LQ];   // 5.76M
__device__ float g_sa   [NQ*DM];
__device__ float g_tmp  [NQ*DM];
__device__ float g_x1   [NQ*DM];
__device__ float g_query[NQ*DM];
__device__ float g_offs [NQ*DM];
__device__ float g_awl  [NQ*NH*NL*NP];
__device__ float g_value[(size_t)MV*DM];          // 165 MB
__device__ float g_samp [NQ*DM];
__device__ float g_x2   [NQ*DM];
__device__ float g_ffh  [NQ*DFF];
__device__ float g_ffn  [NQ*DM];

// ---------------- elementwise add ----------------
__global__ void add2_kernel(const float* __restrict__ a, const float* __restrict__ b,
                            float* __restrict__ o, int n) {
    int i = blockIdx.x * blockDim.x + threadIdx.x;
    if (i < n) o[i] = a[i] + b[i];
}

// ---------------- generic SGEMM: C[M,N] = A[M,K] @ W[N,K]^T + bias ----------
// BM=128 BN=64 BK=16, 256 threads, 8x4 register tile per thread.
// N must be a multiple of 64 (true for all call sites). M edge guarded.
__global__ void gemm_kernel(const float* __restrict__ A, int lda,
                            const float* __restrict__ W, int K,
                            const float* __restrict__ bias,
                            float* __restrict__ C, int ldc,
                            int M, int relu,
                            const unsigned char* __restrict__ rowmask)
{
    __shared__ float sA[16][132];
    __shared__ float sB[16][68];
    const int bm = blockIdx.y * 128;
    const int bn = blockIdx.x * 64;
    const int tid = threadIdx.x;
    const int tr = tid >> 4;      // 0..15 -> rows tr*8..tr*8+7
    const int tc = tid & 15;      // 0..15 -> cols tc*4..tc*4+3

    float acc[8][4];
#pragma unroll
    for (int i = 0; i < 8; i++)
#pragma unroll
        for (int j = 0; j < 4; j++) acc[i][j] = 0.f;

    for (int k0 = 0; k0 < K; k0 += 16) {
        // A tile: 128 rows x 16 cols -> 512 float4, 2 per thread
#pragma unroll
        for (int it = 0; it < 2; it++) {
            int idx = tid + it * 256;
            int m = idx >> 2, kq = idx & 3;
            float4 v = make_float4(0.f, 0.f, 0.f, 0.f);
            if (bm + m < M)
                v = *reinterpret_cast<const float4*>(A + (size_t)(bm + m) * lda + k0 + kq * 4);
            sA[kq * 4 + 0][m] = v.x;
            sA[kq * 4 + 1][m] = v.y;
            sA[kq * 4 + 2][m] = v.z;
            sA[kq * 4 + 3][m] = v.w;
        }
        // B tile: 64 rows x 16 cols -> 256 float4, 1 per thread
        {
            int n = tid >> 2, kq = tid & 3;
            float4 v = *reinterpret_cast<const float4*>(W + (size_t)(bn + n) * K + k0 + kq * 4);
            sB[kq * 4 + 0][n] = v.x;
            sB[kq * 4 + 1][n] = v.y;
            sB[kq * 4 + 2][n] = v.z;
            sB[kq * 4 + 3][n] = v.w;
        }
        __syncthreads();
#pragma unroll
        for (int k = 0; k < 16; k++) {
            float4 a0 = *reinterpret_cast<const float4*>(&sA[k][tr * 8]);
            float4 a1 = *reinterpret_cast<const float4*>(&sA[k][tr * 8 + 4]);
            float4 bv = *reinterpret_cast<const float4*>(&sB[k][tc * 4]);
            float a[8] = {a0.x, a0.y, a0.z, a0.w, a1.x, a1.y, a1.z, a1.w};
            float b[4] = {bv.x, bv.y, bv.z, bv.w};
#pragma unroll
            for (int i = 0; i < 8; i++)
#pragma unroll
                for (int j = 0; j < 4; j++)
                    acc[i][j] = fmaf(a[i], b[j], acc[i][j]);
        }
        __syncthreads();
    }

#pragma unroll
    for (int i = 0; i < 8; i++) {
        int gm = bm + tr * 8 + i;
        if (gm >= M) continue;
        bool mz = (rowmask != nullptr) && rowmask[gm];
#pragma unroll
        for (int j = 0; j < 4; j++) {
            int gn = bn + tc * 4 + j;
            float v = acc[i][j] + bias[gn];
            if (relu) v = fmaxf(v, 0.f);
            if (mz) v = 0.f;
            C[(size_t)gm * ldc + gn] = v;
        }
    }
}

// ---------------- self-attn scores: scores[bh,i,j] = q.k / sqrt(32) --------
__global__ void scores_kernel(const float* __restrict__ qkv, float* __restrict__ scores)
{
    __shared__ float sq[16][33];
    __shared__ float sk[16][33];
    int bh = blockIdx.z;            // b*NH + h
    int b = bh >> 3, h = bh & 7;
    int i0 = blockIdx.y * 16, j0 = blockIdx.x * 16;
    int tx = threadIdx.x, ty = threadIdx.y;
    int t = ty * 16 + tx;

#pragma unroll
    for (int it = 0; it < 2; it++) {
        int idx = t + it * 256;     // 0..511
        int r = idx >> 5, d = idx & 31;
        float qv = 0.f, kv = 0.f;
        if (i0 + r < LQ) qv = qkv[(size_t)(b * LQ + i0 + r) * 768 + h * 32 + d];
        if (j0 + r < LQ) kv = qkv[(size_t)(b * LQ + j0 + r) * 768 + 256 + h * 32 + d];
        sq[r][d] = qv;
        sk[r][d] = kv;
    }
    __syncthreads();
    if (i0 + ty < LQ && j0 + tx < LQ) {
        float s = 0.f;
#pragma unroll
        for (int d = 0; d < 32; d++) s = fmaf(sq[ty][d], sk[tx][d], s);
        scores[((size_t)bh * LQ + i0 + ty) * LQ + j0 + tx] = s * 0.1767766952966369f;
    }
}

// ---------------- softmax over last dim (rows of length 300) ---------------
__global__ void softmax300_kernel(float* __restrict__ scores)
{
    int warp = (blockIdx.x * blockDim.x + threadIdx.x) >> 5;
    int lane = threadIdx.x & 31;
    if (warp >= BB * NH * LQ) return;
    float* row = scores + (size_t)warp * LQ;
    float mx = -1e30f;
    for (int j = lane; j < LQ; j += 32) mx = fmaxf(mx, row[j]);
#pragma unroll
    for (int o = 16; o; o >>= 1) mx = fmaxf(mx, __shfl_xor_sync(0xffffffffu, mx, o));
    float s = 0.f;
    for (int j = lane; j < LQ; j += 32) { float e = __expf(row[j] - mx); row[j] = e; s += e; }
#pragma unroll
    for (int o = 16; o; o >>= 1) s += __shfl_xor_sync(0xffffffffu, s, o);
    float inv = 1.f / s;
    for (int j = lane; j < LQ; j += 32) row[j] *= inv;
}

// ---------------- attn @ v ----------------
__global__ void attnv_kernel(const float* __restrict__ attn, const float* __restrict__ qkv,
                             float* __restrict__ sa)
{
    int bi = blockIdx.x;                 // b*LQ + i
    int b = bi / LQ, i = bi % LQ;
    int t = threadIdx.x;                 // h*32+d
    int h = t >> 5;
    const float* arow = attn + ((size_t)(b * NH + h) * LQ + i) * LQ;
    const float* vb = qkv + 512 + t;
    float acc = 0.f;
    for (int j = 0; j < LQ; j++)
        acc = fmaf(arow[j], vb[(size_t)(b * LQ + j) * 768], acc);
    sa[(size_t)bi * DM + t] = acc;
}

// ---------------- residual + layernorm (+ optional query out) --------------
__global__ void add_ln_kernel(const float* __restrict__ A, const float* __restrict__ R,
                              const float* __restrict__ w, const float* __restrict__ bias,
                              float* __restrict__ out,
                              const float* __restrict__ qpos, float* __restrict__ qout)
{
    __shared__ float sm[8];
    int row = blockIdx.x, t = threadIdx.x;
    size_t base = (size_t)row * DM + t;
    float v = A[base] + R[base];

    float s = v;
#pragma unroll
    for (int o = 16; o; o >>= 1) s += __shfl_xor_sync(0xffffffffu, s, o);
    if ((t & 31) == 0) sm[t >> 5] = s;
    __syncthreads();
    float mean = (sm[0]+sm[1]+sm[2]+sm[3]+sm[4]+sm[5]+sm[6]+sm[7]) * (1.f/DM);
    __syncthreads();

    float d = v - mean;
    float s2 = d * d;
#pragma unroll
    for (int o = 16; o; o >>= 1) s2 += __shfl_xor_sync(0xffffffffu, s2, o);
    if ((t & 31) == 0) sm[t >> 5] = s2;
    __syncthreads();
    float var = (sm[0]+sm[1]+sm[2]+sm[3]+sm[4]+sm[5]+sm[6]+sm[7]) * (1.f/DM);

    float y = d * rsqrtf(var + 1e-5f) * w[t] + bias[t];
    out[base] = y;
    if (qout) qout[base] = y + qpos[base];
}

// ---------------- deformable sampling: one warp per (b,q,h) ----------------
// writes loc, aw to d_out regions and samp accumulator
__global__ void sampling_kernel(const float* __restrict__ refp, const float* __restrict__ offs,
                                const float* __restrict__ awl, const float* __restrict__ value,
                                float* __restrict__ samp,
                                float* __restrict__ out_loc, float* __restrict__ out_aw)
{
    int warp = (blockIdx.x * blockDim.x + threadIdx.x) >> 5;
    int lane = threadIdx.x & 31;
    if (warp >= NQ * NH) return;
    int h = warp & 7;
    int bq = warp >> 3;                  // b*LQ + q
    int b = bq / LQ;

    // attention-weight softmax over 16 (lanes 0..15 hold logits)
    float logit = (lane < 16) ? awl[(size_t)bq * 128 + h * 16 + lane] : -1e30f;
    float mx = logit;
#pragma unroll
    for (int o = 8; o; o >>= 1) mx = fmaxf(mx, __shfl_xor_sync(0xffffffffu, mx, o));
    float e = (lane < 16) ? __expf(logit - mx) : 0.f;
    float ssum = e;
#pragma unroll
    for (int o = 8; o; o >>= 1) ssum += __shfl_xor_sync(0xffffffffu, ssum, o);
    float myaw = (lane < 16) ? (e / ssum) : 0.f;
    if (lane < 16) out_aw[(size_t)(bq * NH + h) * 16 + lane] = myaw;

    const float* vbase = value + (size_t)b * LV * DM + h * 32 + lane;
    float acc = 0.f;

#pragma unroll
    for (int k = 0; k < 16; k++) {
        int l = k >> 2;
        float Wf = (float)c_W[l], Hf = (float)c_H[l];
        int   Wi = c_W[l], Hi = c_H[l], s0 = c_S0[l];

        float rx = refp[(size_t)(bq * NL + l) * 2 + 0];
        float ry = refp[(size_t)(bq * NL + l) * 2 + 1];
        float ox = offs[(size_t)bq * DM + ((h * NL + l) * NP + (k & 3)) * 2 + 0];
        float oy = offs[(size_t)bq * DM + ((h * NL + l) * NP + (k & 3)) * 2 + 1];
        float locx = rx + ox / Wf;
        float locy = ry + oy / Hf;
        if (lane == 0) {
            size_t lo = ((size_t)(bq * NH + h) * 16 + k) * 2;
            out_loc[lo + 0] = locx;
            out_loc[lo + 1] = locy;
        }
        float awk = __shfl_sync(0xffffffffu, myaw, k);

        float x = locx * Wf - 0.5f;
        float y = locy * Hf - 0.5f;
        float x0f = floorf(x), y0f = floorf(y);
        float lx = x - x0f, ly = y - y0f;
        int x0 = (int)x0f, y0 = (int)y0f;

        float sv = 0.f;
#pragma unroll
        for (int c = 0; c < 4; c++) {
            int ix = x0 + (c & 1);
            int iy = y0 + (c >> 1);
            float wgt = ((c & 1) ? lx : 1.f - lx) * ((c >> 1) ? ly : 1.f - ly);
            bool valid = (ix >= 0) && (ix < Wi) && (iy >= 0) && (iy < Hi);
            int cix = min(max(ix, 0), Wi - 1);
            int ciy = min(max(iy, 0), Hi - 1);
            float g = vbase[(size_t)(s0 + ciy * Wi + cix) * DM];
            sv = fmaf(g, valid ? wgt : 0.f, sv);
        }
        acc = fmaf(awk, sv, acc);
    }
    samp[(size_t)bq * DM + h * 32 + lane] = acc;
}

// ---------------- launch ----------------
extern "C" void kernel_launch(void* const* d_in, const int* in_sizes, int n_in,
                              void* d_out, int out_size)
{
    const float* tgt  = (const float*)d_in[0];
    const float* qpos = (const float*)d_in[1];
    const float* refp = (const float*)d_in[2];
    const float* src  = (const float*)d_in[3];
    const float* in_w = (const float*)d_in[4];
    const float* in_b = (const float*)d_in[5];
    const float* out_w= (const float*)d_in[6];
    const float* out_b= (const float*)d_in[7];
    const float* so_w = (const float*)d_in[8];
    const float* so_b = (const float*)d_in[9];
    const float* aw_w = (const float*)d_in[10];
    const float* aw_b = (const float*)d_in[11];
    const float* vp_w = (const float*)d_in[12];
    const float* vp_b = (const float*)d_in[13];
    const float* op_w = (const float*)d_in[14];
    const float* op_b = (const float*)d_in[15];
    const float* l1_w = (const float*)d_in[16];
    const float* l1_b = (const float*)d_in[17];
    const float* l2_w = (const float*)d_in[18];
    const float* l2_b = (const float*)d_in[19];
    const float* n1w  = (const float*)d_in[20];
    const float* n1b  = (const float*)d_in[21];
    const float* n2w  = (const float*)d_in[22];
    const float* n2b  = (const float*)d_in[23];
    const float* n3w  = (const float*)d_in[24];
    const float* n3b  = (const float*)d_in[25];
    // d_in[26] spatial_shapes (int64), d_in[27] level_start_index (int64): hardcoded
    const unsigned char* pmask = (const unsigned char*)d_in[28];
    float* out = (float*)d_out;

    float *qk, *qkv, *scores, *sa, *tmp, *x1, *query, *offs, *awl, *value, *samp, *x2, *ffh, *ffn;
    cudaGetSymbolAddress((void**)&qk,    g_qk);
    cudaGetSymbolAddress((void**)&qkv,   g_qkv);
    cudaGetSymbolAddress((void**)&scores,g_scores);
    cudaGetSymbolAddress((void**)&sa,    g_sa);
    cudaGetSymbolAddress((void**)&tmp,   g_tmp);
    cudaGetSymbolAddress((void**)&x1,    g_x1);
    cudaGetSymbolAddress((void**)&query, g_query);
    cudaGetSymbolAddress((void**)&offs,  g_offs);
    cudaGetSymbolAddress((void**)&awl,   g_awl);
    cudaGetSymbolAddress((void**)&value, g_value);
    cudaGetSymbolAddress((void**)&samp,  g_samp);
    cudaGetSymbolAddress((void**)&x2,    g_x2);
    cudaGetSymbolAddress((void**)&ffh,   g_ffh);
    cudaGetSymbolAddress((void**)&ffn,   g_ffn);

    const int MT = (NQ + 127) / 128;      // 19
    const int MVT = (MV + 127) / 128;     // 1263

    // qk = tgt + query_pos
    add2_kernel<<<(NQ * DM + 255) / 256, 256>>>(tgt, qpos, qk, NQ * DM);

    // QKV projection
    gemm_kernel<<<dim3(8, MT), 256>>>(qk, DM, in_w, DM, in_b, qkv, 768, NQ, 0, nullptr);
    gemm_kernel<<<dim3(4, MT), 256>>>(tgt, DM, in_w + 512 * DM, DM, in_b + 512, qkv + 512, 768, NQ, 0, nullptr);

    // self-attention
    scores_kernel<<<dim3(19, 19, BB * NH), dim3(16, 16)>>>(qkv, scores);
    softmax300_kernel<<<(BB * NH * LQ * 32 + 255) / 256, 256>>>(scores);
    attnv_kernel<<<NQ, 256>>>(scores, qkv, sa);
    gemm_kernel<<<dim3(4, MT), 256>>>(sa, DM, out_w, DM, out_b, tmp, DM, NQ, 0, nullptr);
    add_ln_kernel<<<NQ, 256>>>(tgt, tmp, n2w, n2b, x1, qpos, query);

    // cross-attention inputs
    gemm_kernel<<<dim3(4, MT), 256>>>(query, DM, so_w, DM, so_b, offs, DM, NQ, 0, nullptr);
    gemm_kernel<<<dim3(2, MT), 256>>>(query, DM, aw_w, DM, aw_b, awl, 128, NQ, 0, nullptr);
    gemm_kernel<<<dim3(4, MVT), 256>>>(src, DM, vp_w, DM, vp_b, value, DM, MV, 0, pmask);

    // deformable sampling (writes loc + aw outputs)
    sampling_kernel<<<(NQ * NH * 32 + 255) / 256, 256>>>(refp, offs, awl, value, samp,
                                                         out + 614400, out + 1228800);

    gemm_kernel<<<dim3(4, MT), 256>>>(samp, DM, op_w, DM, op_b, tmp, DM, NQ, 0, nullptr);
    add_ln_kernel<<<NQ, 256>>>(x1, tmp, n1w, n1b, x2, nullptr, nullptr);

    // FFN
    gemm_kernel<<<dim3(16, MT), 256>>>(x2, DM, l1_w, DM, l1_b, ffh, DFF, NQ, 1, nullptr);
    gemm_kernel<<<dim3(4, MT), 256>>>(ffh, DFF, l2_w, DFF, l2_b, ffn, DM, NQ, 0, nullptr);
    add_ln_kernel<<<NQ, 256>>>(x2, ffn, n3w, n3b, out, nullptr, nullptr);
}

// round 5
// speedup vs baseline: 1.5888x; 1.5888x over previous
#include <cuda_runtime.h>
#include <cstdint>
#include <math.h>

// ---------------- problem constants (fixed by reference_code) ----------------
#define BB   8
#define LQ   300
#define DM   256
#define NH   8
#define HD   32
#define NL   4
#define NP   4
#define DFF  1024
#define LV   20197
#define NQ   (BB*LQ)          // 2400
#define MV   (BB*LV)          // 161576

// level constants
__device__ __constant__ int   c_H[NL]  = {100, 50, 25, 13};
__device__ __constant__ int   c_W[NL]  = {152, 76, 38, 19};
__device__ __constant__ int   c_S0[NL] = {0, 15200, 19000, 19950};

// ---------------- scratch (device globals; no allocations allowed) ----------
__device__ float g_qk   [NQ*DM];
__device__ float g_qkv  [NQ*3*DM];
__device__ float g_scores[(size_t)BB*NH*LQ*LQ];   // 5.76M
__device__ float g_sa   [NQ*DM];
__device__ float g_tmp  [NQ*DM];
__device__ float g_x1   [NQ*DM];
__device__ float g_query[NQ*DM];
__device__ float g_offs [NQ*DM];
__device__ float g_awl  [NQ*NH*NL*NP];
__device__ float g_value[(size_t)MV*DM];          // 165 MB
__device__ float g_samp [NQ*DM];
__device__ float g_x2   [NQ*DM];
__device__ float g_ffh  [NQ*DFF];
__device__ float g_ffn  [NQ*DM];

// ---------------- elementwise add ----------------
__global__ void add2_kernel(const float* __restrict__ a, const float* __restrict__ b,
                            float* __restrict__ o, int n) {
    int i = blockIdx.x * blockDim.x + threadIdx.x;
    if (i < n) o[i] = a[i] + b[i];
}

// ---------------- tf32 helpers ----------------
__device__ __forceinline__ uint32_t f2tf32(float f) {
    uint32_t r;
    asm("cvt.rna.tf32.f32 %0, %1;" : "=r"(r) : "f"(f));
    return r;
}

__device__ __forceinline__ void mma_tf32(float c[4],
                                         uint32_t a0, uint32_t a1, uint32_t a2, uint32_t a3,
                                         uint32_t b0, uint32_t b1) {
    asm volatile(
        "mma.sync.aligned.m16n8k8.row.col.f32.tf32.tf32.f32 "
        "{%0,%1,%2,%3}, {%4,%5,%6,%7}, {%8,%9}, {%0,%1,%2,%3};"
        : "+f"(c[0]), "+f"(c[1]), "+f"(c[2]), "+f"(c[3])
        : "r"(a0), "r"(a1), "r"(a2), "r"(a3), "r"(b0), "r"(b1));
}

// ---------------- tf32 tensor-core GEMM: C[M,N] = A[M,K] @ W[N,K]^T + bias --
// BM=128 BN=128 BK=16, 256 threads (8 warps in 2x4), warp tile 64x32.
// Smem pitch GP=20 words -> (r*20+c)%32 is a perfect bank permutation for
// r in [0,8), c in [0,4): all fragment LDS are conflict-free.
// Requires: N % 128 == 0, K % 16 == 0 (true for all call sites). M guarded.
#define GP 20

__global__ __launch_bounds__(256) void gemm_tf32_kernel(
    const float* __restrict__ A, int lda,
    const float* __restrict__ W, int K,
    const float* __restrict__ bias,
    float* __restrict__ C, int ldc,
    int M, int relu,
    const unsigned char* __restrict__ rowmask)
{
    __shared__ uint32_t sA[128 * GP];
    __shared__ uint32_t sB[128 * GP];

    const int bm = blockIdx.y * 128;
    const int bn = blockIdx.x * 128;
    const int tid  = threadIdx.x;
    const int warp = tid >> 5;
    const int lane = tid & 31;
    const int wm = (warp & 1) * 64;     // warp row offset
    const int wn = (warp >> 1) * 32;    // warp col offset
    const int grp = lane >> 2;          // 0..7
    const int tig = lane & 3;           // 0..3

    float acc[4][4][4];                 // [mt][nt][frag]
#pragma unroll
    for (int i = 0; i < 4; i++)
#pragma unroll
        for (int j = 0; j < 4; j++)
#pragma unroll
            for (int c = 0; c < 4; c++) acc[i][j][c] = 0.f;

    for (int k0 = 0; k0 < K; k0 += 16) {
        // fill A tile: 128 rows x 16 k (512 float4 total, 2 per thread)
#pragma unroll
        for (int it = 0; it < 2; it++) {
            int idx = tid + it * 256;
            int m = idx >> 2, kq = idx & 3;
            float4 v = make_float4(0.f, 0.f, 0.f, 0.f);
            if (bm + m < M)
                v = *reinterpret_cast<const float4*>(A + (size_t)(bm + m) * lda + k0 + kq * 4);
            uint32_t* d = &sA[m * GP + kq * 4];
            d[0] = f2tf32(v.x); d[1] = f2tf32(v.y); d[2] = f2tf32(v.z); d[3] = f2tf32(v.w);
        }
        // fill B tile: 128 n-rows x 16 k
#pragma unroll
        for (int it = 0; it < 2; it++) {
            int idx = tid + it * 256;
            int n = idx >> 2, kq = idx & 3;
            float4 v = *reinterpret_cast<const float4*>(W + (size_t)(bn + n) * K + k0 + kq * 4);
            uint32_t* d = &sB[n * GP + kq * 4];
            d[0] = f2tf32(v.x); d[1] = f2tf32(v.y); d[2] = f2tf32(v.z); d[3] = f2tf32(v.w);
        }
        __syncthreads();

#pragma unroll
        for (int ks = 0; ks < 16; ks += 8) {
            uint32_t b[4][2];
#pragma unroll
            for (int nt = 0; nt < 4; nt++) {
                int col = wn + nt * 8 + grp;
                b[nt][0] = sB[col * GP + ks + tig];
                b[nt][1] = sB[col * GP + ks + tig + 4];
            }
#pragma unroll
            for (int mt = 0; mt < 4; mt++) {
                int row = wm + mt * 16 + grp;
                uint32_t a0 = sA[row * GP + ks + tig];
                uint32_t a1 = sA[(row + 8) * GP + ks + tig];
                uint32_t a2 = sA[row * GP + ks + tig + 4];
                uint32_t a3 = sA[(row + 8) * GP + ks + tig + 4];
#pragma unroll
                for (int nt = 0; nt < 4; nt++)
                    mma_tf32(acc[mt][nt], a0, a1, a2, a3, b[nt][0], b[nt][1]);
            }
        }
        __syncthreads();
    }

    // epilogue
#pragma unroll
    for (int mt = 0; mt < 4; mt++) {
#pragma unroll
        for (int half = 0; half < 2; half++) {
            int gm = bm + wm + mt * 16 + grp + half * 8;
            if (gm >= M) continue;
            bool mz = (rowmask != nullptr) && rowmask[gm];
#pragma unroll
            for (int nt = 0; nt < 4; nt++) {
                int gn = bn + wn + nt * 8 + 2 * tig;
                float v0 = acc[mt][nt][half * 2 + 0] + bias[gn];
                float v1 = acc[mt][nt][half * 2 + 1] + bias[gn + 1];
                if (relu) { v0 = fmaxf(v0, 0.f); v1 = fmaxf(v1, 0.f); }
                if (mz) { v0 = 0.f; v1 = 0.f; }
                float2* o = reinterpret_cast<float2*>(C + (size_t)gm * ldc + gn);
                *o = make_float2(v0, v1);
            }
        }
    }
}

// ---------------- self-attn scores: scores[bh,i,j] = q.k / sqrt(32) --------
__global__ void scores_kernel(const float* __restrict__ qkv, float* __restrict__ scores)
{
    __shared__ float sq[16][33];
    __shared__ float sk[16][33];
    int bh = blockIdx.z;            // b*NH + h
    int b = bh >> 3, h = bh & 7;
    int i0 = blockIdx.y * 16, j0 = blockIdx.x * 16;
    int tx = threadIdx.x, ty = threadIdx.y;
    int t = ty * 16 + tx;

#pragma unroll
    for (int it = 0; it < 2; it++) {
        int idx = t + it * 256;     // 0..511
        int r = idx >> 5, d = idx & 31;
        float qv = 0.f, kv = 0.f;
        if (i0 + r < LQ) qv = qkv[(size_t)(b * LQ + i0 + r) * 768 + h * 32 + d];
        if (j0 + r < LQ) kv = qkv[(size_t)(b * LQ + j0 + r) * 768 + 256 + h * 32 + d];
        sq[r][d] = qv;
        sk[r][d] = kv;
    }
    __syncthreads();
    if (i0 + ty < LQ && j0 + tx < LQ) {
        float s = 0.f;
#pragma unroll
        for (int d = 0; d < 32; d++) s = fmaf(sq[ty][d], sk[tx][d], s);
        scores[((size_t)bh * LQ + i0 + ty) * LQ + j0 + tx] = s * 0.1767766952966369f;
    }
}

// ---------------- softmax over last dim (rows of length 300) ---------------
__global__ void softmax300_kernel(float* __restrict__ scores)
{
    int warp = (blockIdx.x * blockDim.x + threadIdx.x) >> 5;
    int lane = threadIdx.x & 31;
    if (warp >= BB * NH * LQ) return;
    float* row = scores + (size_t)warp * LQ;
    float mx = -1e30f;
    for (int j = lane; j < LQ; j += 32) mx = fmaxf(mx, row[j]);
#pragma unroll
    for (int o = 16; o; o >>= 1) mx = fmaxf(mx, __shfl_xor_sync(0xffffffffu, mx, o));
    float s = 0.f;
    for (int j = lane; j < LQ; j += 32) { float e = __expf(row[j] - mx); row[j] = e; s += e; }
#pragma unroll
    for (int o = 16; o; o >>= 1) s += __shfl_xor_sync(0xffffffffu, s, o);
    float inv = 1.f / s;
    for (int j = lane; j < LQ; j += 32) row[j] *= inv;
}

// ---------------- attn @ v ----------------
__global__ void attnv_kernel(const float* __restrict__ attn, const float* __restrict__ qkv,
                             float* __restrict__ sa)
{
    int bi = blockIdx.x;                 // b*LQ + i
    int b = bi / LQ, i = bi % LQ;
    int t = threadIdx.x;                 // h*32+d
    int h = t >> 5;
    const float* arow = attn + ((size_t)(b * NH + h) * LQ + i) * LQ;
    const float* vb = qkv + 512 + t;
    float acc = 0.f;
    for (int j = 0; j < LQ; j++)
        acc = fmaf(arow[j], vb[(size_t)(b * LQ + j) * 768], acc);
    sa[(size_t)bi * DM + t] = acc;
}

// ---------------- residual + layernorm (+ optional query out) --------------
__global__ void add_ln_kernel(const float* __restrict__ A, const float* __restrict__ R,
                              const float* __restrict__ w, const float* __restrict__ bias,
                              float* __restrict__ out,
                              const float* __restrict__ qpos, float* __restrict__ qout)
{
    __shared__ float sm[8];
    int row = blockIdx.x, t = threadIdx.x;
    size_t base = (size_t)row * DM + t;
    float v = A[base] + R[base];

    float s = v;
#pragma unroll
    for (int o = 16; o; o >>= 1) s += __shfl_xor_sync(0xffffffffu, s, o);
    if ((t & 31) == 0) sm[t >> 5] = s;
    __syncthreads();
    float mean = (sm[0]+sm[1]+sm[2]+sm[3]+sm[4]+sm[5]+sm[6]+sm[7]) * (1.f/DM);
    __syncthreads();

    float d = v - mean;
    float s2 = d * d;
#pragma unroll
    for (int o = 16; o; o >>= 1) s2 += __shfl_xor_sync(0xffffffffu, s2, o);
    if ((t & 31) == 0) sm[t >> 5] = s2;
    __syncthreads();
    float var = (sm[0]+sm[1]+sm[2]+sm[3]+sm[4]+sm[5]+sm[6]+sm[7]) * (1.f/DM);

    float y = d * rsqrtf(var + 1e-5f) * w[t] + bias[t];
    out[base] = y;
    if (qout) qout[base] = y + qpos[base];
}

// ---------------- deformable sampling: one warp per (b,q,h) ----------------
__global__ void sampling_kernel(const float* __restrict__ refp, const float* __restrict__ offs,
                                const float* __restrict__ awl, const float* __restrict__ value,
                                float* __restrict__ samp,
                                float* __restrict__ out_loc, float* __restrict__ out_aw)
{
    int warp = (blockIdx.x * blockDim.x + threadIdx.x) >> 5;
    int lane = threadIdx.x & 31;
    if (warp >= NQ * NH) return;
    int h = warp & 7;
    int bq = warp >> 3;                  // b*LQ + q
    int b = bq / LQ;

    float logit = (lane < 16) ? awl[(size_t)bq * 128 + h * 16 + lane] : -1e30f;
    float mx = logit;
#pragma unroll
    for (int o = 8; o; o >>= 1) mx = fmaxf(mx, __shfl_xor_sync(0xffffffffu, mx, o));
    float e = (lane < 16) ? __expf(logit - mx) : 0.f;
    float ssum = e;
#pragma unroll
    for (int o = 8; o; o >>= 1) ssum += __shfl_xor_sync(0xffffffffu, ssum, o);
    float myaw = (lane < 16) ? (e / ssum) : 0.f;
    if (lane < 16) out_aw[(size_t)(bq * NH + h) * 16 + lane] = myaw;

    const float* vbase = value + (size_t)b * LV * DM + h * 32 + lane;
    float acc = 0.f;

#pragma unroll
    for (int k = 0; k < 16; k++) {
        int l = k >> 2;
        float Wf = (float)c_W[l], Hf = (float)c_H[l];
        int   Wi = c_W[l], Hi = c_H[l], s0 = c_S0[l];

        float rx = refp[(size_t)(bq * NL + l) * 2 + 0];
        float ry = refp[(size_t)(bq * NL + l) * 2 + 1];
        float ox = offs[(size_t)bq * DM + ((h * NL + l) * NP + (k & 3)) * 2 + 0];
        float oy = offs[(size_t)bq * DM + ((h * NL + l) * NP + (k & 3)) * 2 + 1];
        float locx = rx + ox / Wf;
        float locy = ry + oy / Hf;
        if (lane == 0) {
            size_t lo = ((size_t)(bq * NH + h) * 16 + k) * 2;
            out_loc[lo + 0] = locx;
            out_loc[lo + 1] = locy;
        }
        float awk = __shfl_sync(0xffffffffu, myaw, k);

        float x = locx * Wf - 0.5f;
        float y = locy * Hf - 0.5f;
        float x0f = floorf(x), y0f = floorf(y);
        float lx = x - x0f, ly = y - y0f;
        int x0 = (int)x0f, y0 = (int)y0f;

        float sv = 0.f;
#pragma unroll
        for (int c = 0; c < 4; c++) {
            int ix = x0 + (c & 1);
            int iy = y0 + (c >> 1);
            float wgt = ((c & 1) ? lx : 1.f - lx) * ((c >> 1) ? ly : 1.f - ly);
            bool valid = (ix >= 0) && (ix < Wi) && (iy >= 0) && (iy < Hi);
            int cix = min(max(ix, 0), Wi - 1);
            int ciy = min(max(iy, 0), Hi - 1);
            float g = vbase[(size_t)(s0 + ciy * Wi + cix) * DM];
            sv = fmaf(g, valid ? wgt : 0.f, sv);
        }
        acc = fmaf(awk, sv, acc);
    }
    samp[(size_t)bq * DM + h * 32 + lane] = acc;
}

// ---------------- launch ----------------
extern "C" void kernel_launch(void* const* d_in, const int* in_sizes, int n_in,
                              void* d_out, int out_size)
{
    const float* tgt  = (const float*)d_in[0];
    const float* qpos = (const float*)d_in[1];
    const float* refp = (const float*)d_in[2];
    const float* src  = (const float*)d_in[3];
    const float* in_w = (const float*)d_in[4];
    const float* in_b = (const float*)d_in[5];
    const float* out_w= (const float*)d_in[6];
    const float* out_b= (const float*)d_in[7];
    const float* so_w = (const float*)d_in[8];
    const float* so_b = (const float*)d_in[9];
    const float* aw_w = (const float*)d_in[10];
    const float* aw_b = (const float*)d_in[11];
    const float* vp_w = (const float*)d_in[12];
    const float* vp_b = (const float*)d_in[13];
    const float* op_w = (const float*)d_in[14];
    const float* op_b = (const float*)d_in[15];
    const float* l1_w = (const float*)d_in[16];
    const float* l1_b = (const float*)d_in[17];
    const float* l2_w = (const float*)d_in[18];
    const float* l2_b = (const float*)d_in[19];
    const float* n1w  = (const float*)d_in[20];
    const float* n1b  = (const float*)d_in[21];
    const float* n2w  = (const float*)d_in[22];
    const float* n2b  = (const float*)d_in[23];
    const float* n3w  = (const float*)d_in[24];
    const float* n3b  = (const float*)d_in[25];
    const unsigned char* pmask = (const unsigned char*)d_in[28];
    float* out = (float*)d_out;

    float *qk, *qkv, *scores, *sa, *tmp, *x1, *query, *offs, *awl, *value, *samp, *x2, *ffh, *ffn;
    cudaGetSymbolAddress((void**)&qk,    g_qk);
    cudaGetSymbolAddress((void**)&qkv,   g_qkv);
    cudaGetSymbolAddress((void**)&scores,g_scores);
    cudaGetSymbolAddress((void**)&sa,    g_sa);
    cudaGetSymbolAddress((void**)&tmp,   g_tmp);
    cudaGetSymbolAddress((void**)&x1,    g_x1);
    cudaGetSymbolAddress((void**)&query, g_query);
    cudaGetSymbolAddress((void**)&offs,  g_offs);
    cudaGetSymbolAddress((void**)&awl,   g_awl);
    cudaGetSymbolAddress((void**)&value, g_value);
    cudaGetSymbolAddress((void**)&samp,  g_samp);
    cudaGetSymbolAddress((void**)&x2,    g_x2);
    cudaGetSymbolAddress((void**)&ffh,   g_ffh);
    cudaGetSymbolAddress((void**)&ffn,   g_ffn);

    const int MT  = (NQ + 127) / 128;     // 19
    const int MVT = (MV + 127) / 128;     // 1263

    // qk = tgt + query_pos
    add2_kernel<<<(NQ * DM + 255) / 256, 256>>>(tgt, qpos, qk, NQ * DM);

    // QKV projection (q,k from qk; v from tgt)
    gemm_tf32_kernel<<<dim3(4, MT), 256>>>(qk, DM, in_w, DM, in_b, qkv, 768, NQ, 0, nullptr);
    gemm_tf32_kernel<<<dim3(2, MT), 256>>>(tgt, DM, in_w + 512 * DM, DM, in_b + 512, qkv + 512, 768, NQ, 0, nullptr);

    // self-attention
    scores_kernel<<<dim3(19, 19, BB * NH), dim3(16, 16)>>>(qkv, scores);
    softmax300_kernel<<<(BB * NH * LQ * 32 + 255) / 256, 256>>>(scores);
    attnv_kernel<<<NQ, 256>>>(scores, qkv, sa);
    gemm_tf32_kernel<<<dim3(2, MT), 256>>>(sa, DM, out_w, DM, out_b, tmp, DM, NQ, 0, nullptr);
    add_ln_kernel<<<NQ, 256>>>(tgt, tmp, n2w, n2b, x1, qpos, query);

    // cross-attention inputs
    gemm_tf32_kernel<<<dim3(2, MT), 256>>>(query, DM, so_w, DM, so_b, offs, DM, NQ, 0, nullptr);
    gemm_tf32_kernel<<<dim3(1, MT), 256>>>(query, DM, aw_w, DM, aw_b, awl, 128, NQ, 0, nullptr);
    gemm_tf32_kernel<<<dim3(2, MVT), 256>>>(src, DM, vp_w, DM, vp_b, value, DM, MV, 0, pmask);

    // deformable sampling (writes loc + aw outputs)
    sampling_kernel<<<(NQ * NH * 32 + 255) / 256, 256>>>(refp, offs, awl, value, samp,
                                                         out + 614400, out + 1228800);

    gemm_tf32_kernel<<<dim3(2, MT), 256>>>(samp, DM, op_w, DM, op_b, tmp, DM, NQ, 0, nullptr);
    add_ln_kernel<<<NQ, 256>>>(x1, tmp, n1w, n1b, x2, nullptr, nullptr);

    // FFN
    gemm_tf32_kernel<<<dim3(8, MT), 256>>>(x2, DM, l1_w, DM, l1_b, ffh, DFF, NQ, 1, nullptr);
    gemm_tf32_kernel<<<dim3(2, MT), 256>>>(ffh, DFF, l2_w, DFF, l2_b, ffn, DM, NQ, 0, nullptr);
    add_ln_kernel<<<NQ, 256>>>(x2, ffn, n3w, n3b, out, nullptr, nullptr);
}

// round 6
// speedup vs baseline: 1.7437x; 1.0975x over previous
#include <cuda_runtime.h>
#include <cstdint>
#include <math.h>

// ---------------- problem constants (fixed by reference_code) ----------------
#define BB   8
#define LQ   300
#define DM   256
#define NH   8
#define HD   32
#define NL   4
#define NP   4
#define DFF  1024
#define LV   20197
#define NQ   (BB*LQ)          // 2400
#define MV   (BB*LV)          // 161576

// level constants
__device__ __constant__ int   c_H[NL]  = {100, 50, 25, 13};
__device__ __constant__ int   c_W[NL]  = {152, 76, 38, 19};
__device__ __constant__ int   c_S0[NL] = {0, 15200, 19000, 19950};

// ---------------- scratch (device globals; no allocations allowed) ----------
__device__ float g_qk   [NQ*DM];
__device__ float g_qkv  [NQ*3*DM];
__device__ float g_sa   [NQ*DM];
__device__ float g_tmp  [NQ*DM];
__device__ float g_x1   [NQ*DM];
__device__ float g_query[NQ*DM];
__device__ float g_offs [NQ*DM];
__device__ float g_awl  [NQ*NH*NL*NP];
__device__ float g_value[(size_t)MV*DM];          // 165 MB
__device__ float g_samp [NQ*DM];
__device__ float g_x2   [NQ*DM];
__device__ float g_ffh  [NQ*DFF];
__device__ float g_ffn  [NQ*DM];

// ---------------- elementwise add ----------------
__global__ void add2_kernel(const float* __restrict__ a, const float* __restrict__ b,
                            float* __restrict__ o, int n) {
    int i = blockIdx.x * blockDim.x + threadIdx.x;
    if (i < n) o[i] = a[i] + b[i];
}

// ---------------- tf32 helpers ----------------
__device__ __forceinline__ uint32_t f2tf32(float f) {
    uint32_t r;
    asm("cvt.rna.tf32.f32 %0, %1;" : "=r"(r) : "f"(f));
    return r;
}

__device__ __forceinline__ void mma_tf32(float c[4],
                                         uint32_t a0, uint32_t a1, uint32_t a2, uint32_t a3,
                                         uint32_t b0, uint32_t b1) {
    asm volatile(
        "mma.sync.aligned.m16n8k8.row.col.f32.tf32.tf32.f32 "
        "{%0,%1,%2,%3}, {%4,%5,%6,%7}, {%8,%9}, {%0,%1,%2,%3};"
        : "+f"(c[0]), "+f"(c[1]), "+f"(c[2]), "+f"(c[3])
        : "r"(a0), "r"(a1), "r"(a2), "r"(a3), "r"(b0), "r"(b1));
}

// ---------------- tf32 tensor-core GEMM: C[M,N] = A[M,K] @ W[N,K]^T + bias --
#define GP 20

__global__ __launch_bounds__(256) void gemm_tf32_kernel(
    const float* __restrict__ A, int lda,
    const float* __restrict__ W, int K,
    const float* __restrict__ bias,
    float* __restrict__ C, int ldc,
    int M, int relu,
    const unsigned char* __restrict__ rowmask)
{
    __shared__ uint32_t sA[128 * GP];
    __shared__ uint32_t sB[128 * GP];

    const int bm = blockIdx.y * 128;
    const int bn = blockIdx.x * 128;
    const int tid  = threadIdx.x;
    const int warp = tid >> 5;
    const int lane = tid & 31;
    const int wm = (warp & 1) * 64;     // warp row offset
    const int wn = (warp >> 1) * 32;    // warp col offset
    const int grp = lane >> 2;          // 0..7
    const int tig = lane & 3;           // 0..3

    float acc[4][4][4];                 // [mt][nt][frag]
#pragma unroll
    for (int i = 0; i < 4; i++)
#pragma unroll
        for (int j = 0; j < 4; j++)
#pragma unroll
            for (int c = 0; c < 4; c++) acc[i][j][c] = 0.f;

    for (int k0 = 0; k0 < K; k0 += 16) {
#pragma unroll
        for (int it = 0; it < 2; it++) {
            int idx = tid + it * 256;
            int m = idx >> 2, kq = idx & 3;
            float4 v = make_float4(0.f, 0.f, 0.f, 0.f);
            if (bm + m < M)
                v = *reinterpret_cast<const float4*>(A + (size_t)(bm + m) * lda + k0 + kq * 4);
            uint32_t* d = &sA[m * GP + kq * 4];
            d[0] = f2tf32(v.x); d[1] = f2tf32(v.y); d[2] = f2tf32(v.z); d[3] = f2tf32(v.w);
        }
#pragma unroll
        for (int it = 0; it < 2; it++) {
            int idx = tid + it * 256;
            int n = idx >> 2, kq = idx & 3;
            float4 v = *reinterpret_cast<const float4*>(W + (size_t)(bn + n) * K + k0 + kq * 4);
            uint32_t* d = &sB[n * GP + kq * 4];
            d[0] = f2tf32(v.x); d[1] = f2tf32(v.y); d[2] = f2tf32(v.z); d[3] = f2tf32(v.w);
        }
        __syncthreads();

#pragma unroll
        for (int ks = 0; ks < 16; ks += 8) {
            uint32_t b[4][2];
#pragma unroll
            for (int nt = 0; nt < 4; nt++) {
                int col = wn + nt * 8 + grp;
                b[nt][0] = sB[col * GP + ks + tig];
                b[nt][1] = sB[col * GP + ks + tig + 4];
            }
#pragma unroll
            for (int mt = 0; mt < 4; mt++) {
                int row = wm + mt * 16 + grp;
                uint32_t a0 = sA[row * GP + ks + tig];
                uint32_t a1 = sA[(row + 8) * GP + ks + tig];
                uint32_t a2 = sA[row * GP + ks + tig + 4];
                uint32_t a3 = sA[(row + 8) * GP + ks + tig + 4];
#pragma unroll
                for (int nt = 0; nt < 4; nt++)
                    mma_tf32(acc[mt][nt], a0, a1, a2, a3, b[nt][0], b[nt][1]);
            }
        }
        __syncthreads();
    }

#pragma unroll
    for (int mt = 0; mt < 4; mt++) {
#pragma unroll
        for (int half = 0; half < 2; half++) {
            int gm = bm + wm + mt * 16 + grp + half * 8;
            if (gm >= M) continue;
            bool mz = (rowmask != nullptr) && rowmask[gm];
#pragma unroll
            for (int nt = 0; nt < 4; nt++) {
                int gn = bn + wn + nt * 8 + 2 * tig;
                float v0 = acc[mt][nt][half * 2 + 0] + bias[gn];
                float v1 = acc[mt][nt][half * 2 + 1] + bias[gn + 1];
                if (relu) { v0 = fmaxf(v0, 0.f); v1 = fmaxf(v1, 0.f); }
                if (mz) { v0 = 0.f; v1 = 0.f; }
                float2* o = reinterpret_cast<float2*>(C + (size_t)gm * ldc + gn);
                *o = make_float2(v0, v1);
            }
        }
    }
}

// ---------------- fused self-attention: scores + softmax + attn@V ----------
// One block per (b, h, q-tile of 24). K/V streamed through smem in 64-row
// chunks; 24x300 score tile resident in smem; softmax in place; then P@V.
#define QT 24
#define KVP 36   // K/V smem pitch (words): 16B-aligned, odd/4-perm -> conflict-free

__global__ __launch_bounds__(256) void attn_fused_kernel(
    const float* __restrict__ qkv, float* __restrict__ sa)
{
    __shared__ float sQ[QT * KVP];
    __shared__ float sKV[64 * KVP];
    __shared__ float sS[QT * 300];

    const int tid = threadIdx.x;
    const int bh = blockIdx.y;          // b*NH + h
    const int b = bh >> 3, h = bh & 7;
    const int q0 = blockIdx.x * QT;

    // load Q tile (pad rows beyond LQ with zeros)
    for (int idx = tid; idx < QT * 32; idx += 256) {
        int r = idx >> 5, d = idx & 31;
        float v = 0.f;
        if (q0 + r < LQ) v = qkv[(size_t)(b * LQ + q0 + r) * 768 + h * 32 + d];
        sQ[r * KVP + d] = v;
    }

    // ---- pass 1: S = Q @ K^T * scale ----
    const int kk = tid & 63;
    const int qb1 = tid >> 6;           // 0..3
    for (int k0 = 0; k0 < LQ; k0 += 64) {
        int kn = min(64, LQ - k0);
        __syncthreads();
        for (int idx = tid; idx < 64 * 32; idx += 256) {
            int r = idx >> 5, d = idx & 31;
            if (r < kn)
                sKV[r * KVP + d] = qkv[(size_t)(b * LQ + k0 + r) * 768 + 256 + h * 32 + d];
        }
        __syncthreads();
        if (kk < kn) {
#pragma unroll
            for (int i = 0; i < QT / 4; i++) {
                int q = qb1 + 4 * i;
                float dot = 0.f;
#pragma unroll
                for (int dq = 0; dq < 8; dq++) {
                    float4 qv = *reinterpret_cast<const float4*>(&sQ[q * KVP + dq * 4]);
                    float4 kv = *reinterpret_cast<const float4*>(&sKV[kk * KVP + dq * 4]);
                    dot = fmaf(qv.x, kv.x, dot);
                    dot = fmaf(qv.y, kv.y, dot);
                    dot = fmaf(qv.z, kv.z, dot);
                    dot = fmaf(qv.w, kv.w, dot);
                }
                sS[q * 300 + k0 + kk] = dot * 0.1767766952966369f;
            }
        }
    }
    __syncthreads();

    // ---- softmax over rows of 300 (8 warps x 3 rows) ----
    {
        int warp = tid >> 5, lane = tid & 31;
#pragma unroll
        for (int i = 0; i < 3; i++) {
            float* row = &sS[(warp + 8 * i) * 300];
            float mx = -1e30f;
            for (int j = lane; j < 300; j += 32) mx = fmaxf(mx, row[j]);
#pragma unroll
            for (int o = 16; o; o >>= 1) mx = fmaxf(mx, __shfl_xor_sync(0xffffffffu, mx, o));
            float s = 0.f;
            for (int j = lane; j < 300; j += 32) { float e = __expf(row[j] - mx); row[j] = e; s += e; }
#pragma unroll
            for (int o = 16; o; o >>= 1) s += __shfl_xor_sync(0xffffffffu, s, o);
            float inv = 1.f / s;
            for (int j = lane; j < 300; j += 32) row[j] *= inv;
        }
    }

    // ---- pass 2: O = P @ V ----
    const int d2 = (tid & 15) * 2;      // pair of channels
    const int qb2 = tid >> 4;           // 0..15
    float acc0 = 0.f, acc1 = 0.f, acc2 = 0.f, acc3 = 0.f;   // q = qb2, qb2+16(pad)
    for (int k0 = 0; k0 < LQ; k0 += 64) {
        int kn = min(64, LQ - k0);
        __syncthreads();
        for (int idx = tid; idx < 64 * 32; idx += 256) {
            int r = idx >> 5, d = idx & 31;
            if (r < kn)
                sKV[r * KVP + d] = qkv[(size_t)(b * LQ + k0 + r) * 768 + 512 + h * 32 + d];
        }
        __syncthreads();
        for (int j = 0; j < kn; j++) {
            float2 vv = *reinterpret_cast<const float2*>(&sKV[j * KVP + d2]);
            float p0 = sS[qb2 * 300 + k0 + j];
            acc0 = fmaf(p0, vv.x, acc0);
            acc1 = fmaf(p0, vv.y, acc1);
            if (qb2 + 16 < QT) {
                float p1 = sS[(qb2 + 16) * 300 + k0 + j];
                acc2 = fmaf(p1, vv.x, acc2);
                acc3 = fmaf(p1, vv.y, acc3);
            }
        }
    }
    // store
    if (q0 + qb2 < LQ) {
        float2* o = reinterpret_cast<float2*>(sa + (size_t)(b * LQ + q0 + qb2) * DM + h * 32 + d2);
        *o = make_float2(acc0, acc1);
    }
    if (qb2 + 16 < QT && q0 + qb2 + 16 < LQ) {
        float2* o = reinterpret_cast<float2*>(sa + (size_t)(b * LQ + q0 + qb2 + 16) * DM + h * 32 + d2);
        *o = make_float2(acc2, acc3);
    }
}

// ---------------- residual + layernorm (+ optional query out) --------------
__global__ void add_ln_kernel(const float* __restrict__ A, const float* __restrict__ R,
                              const float* __restrict__ w, const float* __restrict__ bias,
                              float* __restrict__ out,
                              const float* __restrict__ qpos, float* __restrict__ qout)
{
    __shared__ float sm[8];
    int row = blockIdx.x, t = threadIdx.x;
    size_t base = (size_t)row * DM + t;
    float v = A[base] + R[base];

    float s = v;
#pragma unroll
    for (int o = 16; o; o >>= 1) s += __shfl_xor_sync(0xffffffffu, s, o);
    if ((t & 31) == 0) sm[t >> 5] = s;
    __syncthreads();
    float mean = (sm[0]+sm[1]+sm[2]+sm[3]+sm[4]+sm[5]+sm[6]+sm[7]) * (1.f/DM);
    __syncthreads();

    float d = v - mean;
    float s2 = d * d;
#pragma unroll
    for (int o = 16; o; o >>= 1) s2 += __shfl_xor_sync(0xffffffffu, s2, o);
    if ((t & 31) == 0) sm[t >> 5] = s2;
    __syncthreads();
    float var = (sm[0]+sm[1]+sm[2]+sm[3]+sm[4]+sm[5]+sm[6]+sm[7]) * (1.f/DM);

    float y = d * rsqrtf(var + 1e-5f) * w[t] + bias[t];
    out[base] = y;
    if (qout) qout[base] = y + qpos[base];
}

// ---------------- deformable sampling: one warp per (b,q,h) ----------------
__global__ void sampling_kernel(const float* __restrict__ refp, const float* __restrict__ offs,
                                const float* __restrict__ awl, const float* __restrict__ value,
                                float* __restrict__ samp,
                                float* __restrict__ out_loc, float* __restrict__ out_aw)
{
    int warp = (blockIdx.x * blockDim.x + threadIdx.x) >> 5;
    int lane = threadIdx.x & 31;
    if (warp >= NQ * NH) return;
    int h = warp & 7;
    int bq = warp >> 3;                  // b*LQ + q
    int b = bq / LQ;

    float logit = (lane < 16) ? awl[(size_t)bq * 128 + h * 16 + lane] : -1e30f;
    float mx = logit;
#pragma unroll
    for (int o = 8; o; o >>= 1) mx = fmaxf(mx, __shfl_xor_sync(0xffffffffu, mx, o));
    float e = (lane < 16) ? __expf(logit - mx) : 0.f;
    float ssum = e;
#pragma unroll
    for (int o = 8; o; o >>= 1) ssum += __shfl_xor_sync(0xffffffffu, ssum, o);
    float myaw = (lane < 16) ? (e / ssum) : 0.f;
    if (lane < 16) out_aw[(size_t)(bq * NH + h) * 16 + lane] = myaw;

    const float* vbase = value + (size_t)b * LV * DM + h * 32 + lane;
    float acc = 0.f;

#pragma unroll
    for (int k = 0; k < 16; k++) {
        int l = k >> 2;
        float Wf = (float)c_W[l], Hf = (float)c_H[l];
        int   Wi = c_W[l], Hi = c_H[l], s0 = c_S0[l];

        float rx = refp[(size_t)(bq * NL + l) * 2 + 0];
        float ry = refp[(size_t)(bq * NL + l) * 2 + 1];
        float ox = offs[(size_t)bq * DM + ((h * NL + l) * NP + (k & 3)) * 2 + 0];
        float oy = offs[(size_t)bq * DM + ((h * NL + l) * NP + (k & 3)) * 2 + 1];
        float locx = rx + ox / Wf;
        float locy = ry + oy / Hf;
        if (lane == 0) {
            size_t lo = ((size_t)(bq * NH + h) * 16 + k) * 2;
            out_loc[lo + 0] = locx;
            out_loc[lo + 1] = locy;
        }
        float awk = __shfl_sync(0xffffffffu, myaw, k);

        float x = locx * Wf - 0.5f;
        float y = locy * Hf - 0.5f;
        float x0f = floorf(x), y0f = floorf(y);
        float lx = x - x0f, ly = y - y0f;
        int x0 = (int)x0f, y0 = (int)y0f;

        float sv = 0.f;
#pragma unroll
        for (int c = 0; c < 4; c++) {
            int ix = x0 + (c & 1);
            int iy = y0 + (c >> 1);
            float wgt = ((c & 1) ? lx : 1.f - lx) * ((c >> 1) ? ly : 1.f - ly);
            bool valid = (ix >= 0) && (ix < Wi) && (iy >= 0) && (iy < Hi);
            int cix = min(max(ix, 0), Wi - 1);
            int ciy = min(max(iy, 0), Hi - 1);
            float g = vbase[(size_t)(s0 + ciy * Wi + cix) * DM];
            sv = fmaf(g, valid ? wgt : 0.f, sv);
        }
        acc = fmaf(awk, sv, acc);
    }
    samp[(size_t)bq * DM + h * 32 + lane] = acc;
}

// ---------------- launch ----------------
extern "C" void kernel_launch(void* const* d_in, const int* in_sizes, int n_in,
                              void* d_out, int out_size)
{
    const float* tgt  = (const float*)d_in[0];
    const float* qpos = (const float*)d_in[1];
    const float* refp = (const float*)d_in[2];
    const float* src  = (const float*)d_in[3];
    const float* in_w = (const float*)d_in[4];
    const float* in_b = (const float*)d_in[5];
    const float* out_w= (const float*)d_in[6];
    const float* out_b= (const float*)d_in[7];
    const float* so_w = (const float*)d_in[8];
    const float* so_b = (const float*)d_in[9];
    const float* aw_w = (const float*)d_in[10];
    const float* aw_b = (const float*)d_in[11];
    const float* vp_w = (const float*)d_in[12];
    const float* vp_b = (const float*)d_in[13];
    const float* op_w = (const float*)d_in[14];
    const float* op_b = (const float*)d_in[15];
    const float* l1_w = (const float*)d_in[16];
    const float* l1_b = (const float*)d_in[17];
    const float* l2_w = (const float*)d_in[18];
    const float* l2_b = (const float*)d_in[19];
    const float* n1w  = (const float*)d_in[20];
    const float* n1b  = (const float*)d_in[21];
    const float* n2w  = (const float*)d_in[22];
    const float* n2b  = (const float*)d_in[23];
    const float* n3w  = (const float*)d_in[24];
    const float* n3b  = (const float*)d_in[25];
    const unsigned char* pmask = (const unsigned char*)d_in[28];
    float* out = (float*)d_out;

    float *qk, *qkv, *sa, *tmp, *x1, *query, *offs, *awl, *value, *samp, *x2, *ffh, *ffn;
    cudaGetSymbolAddress((void**)&qk,    g_qk);
    cudaGetSymbolAddress((void**)&qkv,   g_qkv);
    cudaGetSymbolAddress((void**)&sa,    g_sa);
    cudaGetSymbolAddress((void**)&tmp,   g_tmp);
    cudaGetSymbolAddress((void**)&x1,    g_x1);
    cudaGetSymbolAddress((void**)&query, g_query);
    cudaGetSymbolAddress((void**)&offs,  g_offs);
    cudaGetSymbolAddress((void**)&awl,   g_awl);
    cudaGetSymbolAddress((void**)&value, g_value);
    cudaGetSymbolAddress((void**)&samp,  g_samp);
    cudaGetSymbolAddress((void**)&x2,    g_x2);
    cudaGetSymbolAddress((void**)&ffh,   g_ffh);
    cudaGetSymbolAddress((void**)&ffn,   g_ffn);

    const int MT  = (NQ + 127) / 128;     // 19
    const int MVT = (MV + 127) / 128;     // 1263

    // qk = tgt + query_pos
    add2_kernel<<<(NQ * DM + 255) / 256, 256>>>(tgt, qpos, qk, NQ * DM);

    // QKV projection (q,k from qk; v from tgt)
    gemm_tf32_kernel<<<dim3(4, MT), 256>>>(qk, DM, in_w, DM, in_b, qkv, 768, NQ, 0, nullptr);
    gemm_tf32_kernel<<<dim3(2, MT), 256>>>(tgt, DM, in_w + 512 * DM, DM, in_b + 512, qkv + 512, 768, NQ, 0, nullptr);

    // fused self-attention (scores + softmax + attn@V)
    attn_fused_kernel<<<dim3((LQ + QT - 1) / QT, BB * NH), 256>>>(qkv, sa);

    gemm_tf32_kernel<<<dim3(2, MT), 256>>>(sa, DM, out_w, DM, out_b, tmp, DM, NQ, 0, nullptr);
    add_ln_kernel<<<NQ, 256>>>(tgt, tmp, n2w, n2b, x1, qpos, query);

    // cross-attention inputs
    gemm_tf32_kernel<<<dim3(2, MT), 256>>>(query, DM, so_w, DM, so_b, offs, DM, NQ, 0, nullptr);
    gemm_tf32_kernel<<<dim3(1, MT), 256>>>(query, DM, aw_w, DM, aw_b, awl, 128, NQ, 0, nullptr);
    gemm_tf32_kernel<<<dim3(2, MVT), 256>>>(src, DM, vp_w, DM, vp_b, value, DM, MV, 0, pmask);

    // deformable sampling (writes loc + aw outputs)
    sampling_kernel<<<(NQ * NH * 32 + 255) / 256, 256>>>(refp, offs, awl, value, samp,
                                                         out + 614400, out + 1228800);

    gemm_tf32_kernel<<<dim3(2, MT), 256>>>(samp, DM, op_w, DM, op_b, tmp, DM, NQ, 0, nullptr);
    add_ln_kernel<<<NQ, 256>>>(x1, tmp, n1w, n1b, x2, nullptr, nullptr);

    // FFN
    gemm_tf32_kernel<<<dim3(8, MT), 256>>>(x2, DM, l1_w, DM, l1_b, ffh, DFF, NQ, 1, nullptr);
    gemm_tf32_kernel<<<dim3(2, MT), 256>>>(ffh, DFF, l2_w, DFF, l2_b, ffn, DM, NQ, 0, nullptr);
    add_ln_kernel<<<NQ, 256>>>(x2, ffn, n3w, n3b, out, nullptr, nullptr);
}

// round 7
// speedup vs baseline: 2.1200x; 1.2158x over previous
#include <cuda_runtime.h>
#include <cstdint>
#include <math.h>

// ---------------- problem constants (fixed by reference_code) ----------------
#define BB   8
#define LQ   300
#define DM   256
#define NH   8
#define HD   32
#define NL   4
#define NP   4
#define DFF  1024
#define LV   20197
#define NQ   (BB*LQ)          // 2400
#define MV   (BB*LV)          // 161576

// level constants
__device__ __constant__ int   c_H[NL]  = {100, 50, 25, 13};
__device__ __constant__ int   c_W[NL]  = {152, 76, 38, 19};
__device__ __constant__ int   c_S0[NL] = {0, 15200, 19000, 19950};

// weight-rounding segment table: in,out,so,aw,vp,op,l1,l2
__device__ __constant__ int c_wsz[8]  = {196608, 65536, 65536, 32768, 65536, 65536, 262144, 262144};
__device__ __constant__ int c_woff[8] = {0, 196608, 262144, 327680, 360448, 425984, 491520, 753664};

// ---------------- scratch (device globals; no allocations allowed) ----------
__device__ float g_qk   [NQ*DM];
__device__ float g_qkv  [NQ*3*DM];
__device__ float g_sa   [NQ*DM];
__device__ float g_tmp  [NQ*DM];
__device__ float g_x1   [NQ*DM];
__device__ float g_query[NQ*DM];
__device__ float g_offs [NQ*DM];
__device__ float g_awl  [NQ*NH*NL*NP];
__device__ float g_value[(size_t)MV*DM];          // 165 MB
__device__ float g_samp [NQ*DM];
__device__ float g_x2   [NQ*DM];
__device__ float g_ffh  [NQ*DFF];
__device__ float g_ffn  [NQ*DM];
__device__ float g_wr   [1015808];                // tf32-rounded weights

// ---------------- elementwise add ----------------
__global__ void add2_kernel(const float* __restrict__ a, const float* __restrict__ b,
                            float* __restrict__ o, int n) {
    int i = blockIdx.x * blockDim.x + threadIdx.x;
    if (i < n) o[i] = a[i] + b[i];
}

// ---------------- tf32 helpers ----------------
__device__ __forceinline__ uint32_t f2tf32(float f) {
    uint32_t r;
    asm("cvt.rna.tf32.f32 %0, %1;" : "=r"(r) : "f"(f));
    return r;
}

__device__ __forceinline__ void mma_tf32(float c[4],
                                         uint32_t a0, uint32_t a1, uint32_t a2, uint32_t a3,
                                         uint32_t b0, uint32_t b1) {
    asm volatile(
        "mma.sync.aligned.m16n8k8.row.col.f32.tf32.tf32.f32 "
        "{%0,%1,%2,%3}, {%4,%5,%6,%7}, {%8,%9}, {%0,%1,%2,%3};"
        : "+f"(c[0]), "+f"(c[1]), "+f"(c[2]), "+f"(c[3])
        : "r"(a0), "r"(a1), "r"(a2), "r"(a3), "r"(b0), "r"(b1));
}

// ---------------- cp.async helpers ----------------
__device__ __forceinline__ void cp16(uint32_t dst, const void* src, int sz) {
    asm volatile("cp.async.cg.shared.global [%0], [%1], 16, %2;" :: "r"(dst), "l"(src), "r"(sz));
}
__device__ __forceinline__ void cp_commit() { asm volatile("cp.async.commit_group;"); }
__device__ __forceinline__ void cp_wait0()  { asm volatile("cp.async.wait_group 0;"); }

// ---------------- round weights to tf32 (rna) once per launch --------------
__global__ void round_w_kernel(const float* __restrict__ p0, const float* __restrict__ p1,
                               const float* __restrict__ p2, const float* __restrict__ p3,
                               const float* __restrict__ p4, const float* __restrict__ p5,
                               const float* __restrict__ p6, const float* __restrict__ p7,
                               float* __restrict__ out)
{
    int m = blockIdx.y;
    int i4 = (blockIdx.x * 256 + threadIdx.x) * 4;
    if (i4 >= c_wsz[m]) return;
    const float* src;
    switch (m) {
        case 0: src = p0; break; case 1: src = p1; break;
        case 2: src = p2; break; case 3: src = p3; break;
        case 4: src = p4; break; case 5: src = p5; break;
        case 6: src = p6; break; default: src = p7; break;
    }
    float4 v = *reinterpret_cast<const float4*>(src + i4);
    v.x = __uint_as_float(f2tf32(v.x));
    v.y = __uint_as_float(f2tf32(v.y));
    v.z = __uint_as_float(f2tf32(v.z));
    v.w = __uint_as_float(f2tf32(v.w));
    *reinterpret_cast<float4*>(out + c_woff[m] + i4) = v;
}

// ---------------- tf32 tensor-core GEMM, cp.async double-buffered ----------
// C[M,N] = A[M,K] @ W[N,K]^T + bias. BM=128 BN=128 BK=16, 256 threads,
// 8 warps 2x4, warp tile 64x32. Smem pitch GP=20 words (bank-conflict-free
// fragment loads; every 16B chunk 16B-aligned since 80 % 16 == 0).
// A fed as raw fp32 bits (hardware tf32 truncation); W must be pre-rounded.
#define GP 20

__global__ __launch_bounds__(256) void gemm_tf32_kernel(
    const float* __restrict__ A, int lda,
    const float* __restrict__ W, int K,
    const float* __restrict__ bias,
    float* __restrict__ C, int ldc,
    int M, int relu,
    const unsigned char* __restrict__ rowmask)
{
    __shared__ uint32_t sA[2][128 * GP];
    __shared__ uint32_t sB[2][128 * GP];

    const int bm = blockIdx.y * 128;
    const int bn = blockIdx.x * 128;
    const int tid  = threadIdx.x;
    const int warp = tid >> 5;
    const int lane = tid & 31;
    const int wm = (warp & 1) * 64;
    const int wn = (warp >> 1) * 32;
    const int grp = lane >> 2;
    const int tig = lane & 3;

    // fill coords: idx = tid + it*256 -> m = tid/4 + it*64, kq = tid%4
    const int mf  = tid >> 2;
    const int kqf = tid & 3;
    const uint32_t sA0 = (uint32_t)__cvta_generic_to_shared(&sA[0][0]);
    const uint32_t sB0 = (uint32_t)__cvta_generic_to_shared(&sB[0][0]);
    const uint32_t stageBytes = 128 * GP * 4;

    const float* aP0 = A + (size_t)(bm + mf)      * lda + kqf * 4;
    const float* aP1 = A + (size_t)(bm + mf + 64) * lda + kqf * 4;
    const int pr0 = (bm + mf      < M) ? 16 : 0;
    const int pr1 = (bm + mf + 64 < M) ? 16 : 0;
    const float* bP0 = W + (size_t)(bn + mf)      * K + kqf * 4;
    const float* bP1 = W + (size_t)(bn + mf + 64) * K + kqf * 4;
    const uint32_t soA0 = sA0 + (mf * GP + kqf * 4) * 4;
    const uint32_t soA1 = sA0 + ((mf + 64) * GP + kqf * 4) * 4;
    const uint32_t soB0 = sB0 + (mf * GP + kqf * 4) * 4;
    const uint32_t soB1 = sB0 + ((mf + 64) * GP + kqf * 4) * 4;

    float acc[4][4][4];
#pragma unroll
    for (int i = 0; i < 4; i++)
#pragma unroll
        for (int j = 0; j < 4; j++)
#pragma unroll
            for (int c = 0; c < 4; c++) acc[i][j][c] = 0.f;

    const int niter = K >> 4;

    // prologue: stage 0
    {
        cp16(soA0, aP0, pr0);
        cp16(soA1, aP1, pr1);
        cp16(soB0, bP0, 16);
        cp16(soB1, bP1, 16);
        cp_commit();
    }

    for (int i = 0; i < niter; i++) {
        const int cur = i & 1;
        cp_wait0();
        __syncthreads();
        if (i + 1 < niter) {
            const int nxt = 1 - cur;
            const int k1 = (i + 1) << 4;
            cp16(soA0 + nxt * stageBytes, aP0 + k1, pr0);
            cp16(soA1 + nxt * stageBytes, aP1 + k1, pr1);
            cp16(soB0 + nxt * stageBytes, bP0 + k1, 16);
            cp16(soB1 + nxt * stageBytes, bP1 + k1, 16);
            cp_commit();
        }
        const uint32_t* cA = &sA[cur][0];
        const uint32_t* cB = &sB[cur][0];
#pragma unroll
        for (int ks = 0; ks < 16; ks += 8) {
            uint32_t b[4][2];
#pragma unroll
            for (int nt = 0; nt < 4; nt++) {
                int col = wn + nt * 8 + grp;
                b[nt][0] = cB[col * GP + ks + tig];
                b[nt][1] = cB[col * GP + ks + tig + 4];
            }
#pragma unroll
            for (int mt = 0; mt < 4; mt++) {
                int row = wm + mt * 16 + grp;
                uint32_t a0 = cA[row * GP + ks + tig];
                uint32_t a1 = cA[(row + 8) * GP + ks + tig];
                uint32_t a2 = cA[row * GP + ks + tig + 4];
                uint32_t a3 = cA[(row + 8) * GP + ks + tig + 4];
#pragma unroll
                for (int nt = 0; nt < 4; nt++)
                    mma_tf32(acc[mt][nt], a0, a1, a2, a3, b[nt][0], b[nt][1]);
            }
        }
        __syncthreads();
    }

    // epilogue
#pragma unroll
    for (int mt = 0; mt < 4; mt++) {
#pragma unroll
        for (int half = 0; half < 2; half++) {
            int gm = bm + wm + mt * 16 + grp + half * 8;
            if (gm >= M) continue;
            bool mz = (rowmask != nullptr) && rowmask[gm];
#pragma unroll
            for (int nt = 0; nt < 4; nt++) {
                int gn = bn + wn + nt * 8 + 2 * tig;
                float v0 = acc[mt][nt][half * 2 + 0] + bias[gn];
                float v1 = acc[mt][nt][half * 2 + 1] + bias[gn + 1];
                if (relu) { v0 = fmaxf(v0, 0.f); v1 = fmaxf(v1, 0.f); }
                if (mz) { v0 = 0.f; v1 = 0.f; }
                float2* o = reinterpret_cast<float2*>(C + (size_t)gm * ldc + gn);
                *o = make_float2(v0, v1);
            }
        }
    }
}

// ---------------- fused self-attention: scores + softmax + attn@V ----------
#define QT 24
#define KVP 36

__global__ __launch_bounds__(256) void attn_fused_kernel(
    const float* __restrict__ qkv, float* __restrict__ sa)
{
    __shared__ float sQ[QT * KVP];
    __shared__ float sKV[64 * KVP];
    __shared__ float sS[QT * 300];

    const int tid = threadIdx.x;
    const int bh = blockIdx.y;
    const int b = bh >> 3, h = bh & 7;
    const int q0 = blockIdx.x * QT;

    for (int idx = tid; idx < QT * 32; idx += 256) {
        int r = idx >> 5, d = idx & 31;
        float v = 0.f;
        if (q0 + r < LQ) v = qkv[(size_t)(b * LQ + q0 + r) * 768 + h * 32 + d];
        sQ[r * KVP + d] = v;
    }

    const int kk = tid & 63;
    const int qb1 = tid >> 6;
    for (int k0 = 0; k0 < LQ; k0 += 64) {
        int kn = min(64, LQ - k0);
        __syncthreads();
        for (int idx = tid; idx < 64 * 32; idx += 256) {
            int r = idx >> 5, d = idx & 31;
            if (r < kn)
                sKV[r * KVP + d] = qkv[(size_t)(b * LQ + k0 + r) * 768 + 256 + h * 32 + d];
        }
        __syncthreads();
        if (kk < kn) {
#pragma unroll
            for (int i = 0; i < QT / 4; i++) {
                int q = qb1 + 4 * i;
                float dot = 0.f;
#pragma unroll
                for (int dq = 0; dq < 8; dq++) {
                    float4 qv = *reinterpret_cast<const float4*>(&sQ[q * KVP + dq * 4]);
                    float4 kv = *reinterpret_cast<const float4*>(&sKV[kk * KVP + dq * 4]);
                    dot = fmaf(qv.x, kv.x, dot);
                    dot = fmaf(qv.y, kv.y, dot);
                    dot = fmaf(qv.z, kv.z, dot);
                    dot = fmaf(qv.w, kv.w, dot);
                }
                sS[q * 300 + k0 + kk] = dot * 0.1767766952966369f;
            }
        }
    }
    __syncthreads();

    {
        int warp = tid >> 5, lane = tid & 31;
#pragma unroll
        for (int i = 0; i < 3; i++) {
            float* row = &sS[(warp + 8 * i) * 300];
            float mx = -1e30f;
            for (int j = lane; j < 300; j += 32) mx = fmaxf(mx, row[j]);
#pragma unroll
            for (int o = 16; o; o >>= 1) mx = fmaxf(mx, __shfl_xor_sync(0xffffffffu, mx, o));
            float s = 0.f;
            for (int j = lane; j < 300; j += 32) { float e = __expf(row[j] - mx); row[j] = e; s += e; }
#pragma unroll
            for (int o = 16; o; o >>= 1) s += __shfl_xor_sync(0xffffffffu, s, o);
            float inv = 1.f / s;
            for (int j = lane; j < 300; j += 32) row[j] *= inv;
        }
    }

    const int d2 = (tid & 15) * 2;
    const int qb2 = tid >> 4;
    float acc0 = 0.f, acc1 = 0.f, acc2 = 0.f, acc3 = 0.f;
    for (int k0 = 0; k0 < LQ; k0 += 64) {
        int kn = min(64, LQ - k0);
        __syncthreads();
        for (int idx = tid; idx < 64 * 32; idx += 256) {
            int r = idx >> 5, d = idx & 31;
            if (r < kn)
                sKV[r * KVP + d] = qkv[(size_t)(b * LQ + k0 + r) * 768 + 512 + h * 32 + d];
        }
        __syncthreads();
        for (int j = 0; j < kn; j++) {
            float2 vv = *reinterpret_cast<const float2*>(&sKV[j * KVP + d2]);
            float p0 = sS[qb2 * 300 + k0 + j];
            acc0 = fmaf(p0, vv.x, acc0);
            acc1 = fmaf(p0, vv.y, acc1);
            if (qb2 + 16 < QT) {
                float p1 = sS[(qb2 + 16) * 300 + k0 + j];
                acc2 = fmaf(p1, vv.x, acc2);
                acc3 = fmaf(p1, vv.y, acc3);
            }
        }
    }
    if (q0 + qb2 < LQ) {
        float2* o = reinterpret_cast<float2*>(sa + (size_t)(b * LQ + q0 + qb2) * DM + h * 32 + d2);
        *o = make_float2(acc0, acc1);
    }
    if (qb2 + 16 < QT && q0 + qb2 + 16 < LQ) {
        float2* o = reinterpret_cast<float2*>(sa + (size_t)(b * LQ + q0 + qb2 + 16) * DM + h * 32 + d2);
        *o = make_float2(acc2, acc3);
    }
}

// ---------------- residual + layernorm (+ optional query out) --------------
__global__ void add_ln_kernel(const float* __restrict__ A, const float* __restrict__ R,
                              const float* __restrict__ w, const float* __restrict__ bias,
                              float* __restrict__ out,
                              const float* __restrict__ qpos, float* __restrict__ qout)
{
    __shared__ float sm[8];
    int row = blockIdx.x, t = threadIdx.x;
    size_t base = (size_t)row * DM + t;
    float v = A[base] + R[base];

    float s = v;
#pragma unroll
    for (int o = 16; o; o >>= 1) s += __shfl_xor_sync(0xffffffffu, s, o);
    if ((t & 31) == 0) sm[t >> 5] = s;
    __syncthreads();
    float mean = (sm[0]+sm[1]+sm[2]+sm[3]+sm[4]+sm[5]+sm[6]+sm[7]) * (1.f/DM);
    __syncthreads();

    float d = v - mean;
    float s2 = d * d;
#pragma unroll
    for (int o = 16; o; o >>= 1) s2 += __shfl_xor_sync(0xffffffffu, s2, o);
    if ((t & 31) == 0) sm[t >> 5] = s2;
    __syncthreads();
    float var = (sm[0]+sm[1]+sm[2]+sm[3]+sm[4]+sm[5]+sm[6]+sm[7]) * (1.f/DM);

    float y = d * rsqrtf(var + 1e-5f) * w[t] + bias[t];
    out[base] = y;
    if (qout) qout[base] = y + qpos[base];
}

// ---------------- deformable sampling: one warp per (b,q,h) ----------------
__global__ void sampling_kernel(const float* __restrict__ refp, const float* __restrict__ offs,
                                const float* __restrict__ awl, const float* __restrict__ value,
                                float* __restrict__ samp,
                                float* __restrict__ out_loc, float* __restrict__ out_aw)
{
    int warp = (blockIdx.x * blockDim.x + threadIdx.x) >> 5;
    int lane = threadIdx.x & 31;
    if (warp >= NQ * NH) return;
    int h = warp & 7;
    int bq = warp >> 3;
    int b = bq / LQ;

    float logit = (lane < 16) ? awl[(size_t)bq * 128 + h * 16 + lane] : -1e30f;
    float mx = logit;
#pragma unroll
    for (int o = 8; o; o >>= 1) mx = fmaxf(mx, __shfl_xor_sync(0xffffffffu, mx, o));
    float e = (lane < 16) ? __expf(logit - mx) : 0.f;
    float ssum = e;
#pragma unroll
    for (int o = 8; o; o >>= 1) ssum += __shfl_xor_sync(0xffffffffu, ssum, o);
    float myaw = (lane < 16) ? (e / ssum) : 0.f;
    if (lane < 16) out_aw[(size_t)(bq * NH + h) * 16 + lane] = myaw;

    const float* vbase = value + (size_t)b * LV * DM + h * 32 + lane;
    float acc = 0.f;

#pragma unroll
    for (int k = 0; k < 16; k++) {
        int l = k >> 2;
        float Wf = (float)c_W[l], Hf = (float)c_H[l];
        int   Wi = c_W[l], Hi = c_H[l], s0 = c_S0[l];

        float rx = refp[(size_t)(bq * NL + l) * 2 + 0];
        float ry = refp[(size_t)(bq * NL + l) * 2 + 1];
        float ox = offs[(size_t)bq * DM + ((h * NL + l) * NP + (k & 3)) * 2 + 0];
        float oy = offs[(size_t)bq * DM + ((h * NL + l) * NP + (k & 3)) * 2 + 1];
        float locx = rx + ox / Wf;
        float locy = ry + oy / Hf;
        if (lane == 0) {
            size_t lo = ((size_t)(bq * NH + h) * 16 + k) * 2;
            out_loc[lo + 0] = locx;
            out_loc[lo + 1] = locy;
        }
        float awk = __shfl_sync(0xffffffffu, myaw, k);

        float x = locx * Wf - 0.5f;
        float y = locy * Hf - 0.5f;
        float x0f = floorf(x), y0f = floorf(y);
        float lx = x - x0f, ly = y - y0f;
        int x0 = (int)x0f, y0 = (int)y0f;

        float sv = 0.f;
#pragma unroll
        for (int c = 0; c < 4; c++) {
            int ix = x0 + (c & 1);
            int iy = y0 + (c >> 1);
            float wgt = ((c & 1) ? lx : 1.f - lx) * ((c >> 1) ? ly : 1.f - ly);
            bool valid = (ix >= 0) && (ix < Wi) && (iy >= 0) && (iy < Hi);
            int cix = min(max(ix, 0), Wi - 1);
            int ciy = min(max(iy, 0), Hi - 1);
            float g = vbase[(size_t)(s0 + ciy * Wi + cix) * DM];
            sv = fmaf(g, valid ? wgt : 0.f, sv);
        }
        acc = fmaf(awk, sv, acc);
    }
    samp[(size_t)bq * DM + h * 32 + lane] = acc;
}

// ---------------- launch ----------------
extern "C" void kernel_launch(void* const* d_in, const int* in_sizes, int n_in,
                              void* d_out, int out_size)
{
    const float* tgt  = (const float*)d_in[0];
    const float* qpos = (const float*)d_in[1];
    const float* refp = (const float*)d_in[2];
    const float* src  = (const float*)d_in[3];
    const float* in_w = (const float*)d_in[4];
    const float* in_b = (const float*)d_in[5];
    const float* out_w= (const float*)d_in[6];
    const float* out_b= (const float*)d_in[7];
    const float* so_w = (const float*)d_in[8];
    const float* so_b = (const float*)d_in[9];
    const float* aw_w = (const float*)d_in[10];
    const float* aw_b = (const float*)d_in[11];
    const float* vp_w = (const float*)d_in[12];
    const float* vp_b = (const float*)d_in[13];
    const float* op_w = (const float*)d_in[14];
    const float* op_b = (const float*)d_in[15];
    const float* l1_w = (const float*)d_in[16];
    const float* l1_b = (const float*)d_in[17];
    const float* l2_w = (const float*)d_in[18];
    const float* l2_b = (const float*)d_in[19];
    const float* n1w  = (const float*)d_in[20];
    const float* n1b  = (const float*)d_in[21];
    const float* n2w  = (const float*)d_in[22];
    const float* n2b  = (const float*)d_in[23];
    const float* n3w  = (const float*)d_in[24];
    const float* n3b  = (const float*)d_in[25];
    const unsigned char* pmask = (const unsigned char*)d_in[28];
    float* out = (float*)d_out;

    float *qk, *qkv, *sa, *tmp, *x1, *query, *offs, *awl, *value, *samp, *x2, *ffh, *ffn, *wr;
    cudaGetSymbolAddress((void**)&qk,    g_qk);
    cudaGetSymbolAddress((void**)&qkv,   g_qkv);
    cudaGetSymbolAddress((void**)&sa,    g_sa);
    cudaGetSymbolAddress((void**)&tmp,   g_tmp);
    cudaGetSymbolAddress((void**)&x1,    g_x1);
    cudaGetSymbolAddress((void**)&query, g_query);
    cudaGetSymbolAddress((void**)&offs,  g_offs);
    cudaGetSymbolAddress((void**)&awl,   g_awl);
    cudaGetSymbolAddress((void**)&value, g_value);
    cudaGetSymbolAddress((void**)&samp,  g_samp);
    cudaGetSymbolAddress((void**)&x2,    g_x2);
    cudaGetSymbolAddress((void**)&ffh,   g_ffh);
    cudaGetSymbolAddress((void**)&ffn,   g_ffn);
    cudaGetSymbolAddress((void**)&wr,    g_wr);

    const int MT  = (NQ + 127) / 128;     // 19
    const int MVT = (MV + 127) / 128;     // 1263

    // pre-round all weight matrices to tf32 (rna)
    round_w_kernel<<<dim3(256, 8), 256>>>(in_w, out_w, so_w, aw_w, vp_w, op_w, l1_w, l2_w, wr);

    const float* w_in  = wr + 0;
    const float* w_out = wr + 196608;
    const float* w_so  = wr + 262144;
    const float* w_aw  = wr + 327680;
    const float* w_vp  = wr + 360448;
    const float* w_op  = wr + 425984;
    const float* w_l1  = wr + 491520;
    const float* w_l2  = wr + 753664;

    // qk = tgt + query_pos
    add2_kernel<<<(NQ * DM + 255) / 256, 256>>>(tgt, qpos, qk, NQ * DM);

    // QKV projection (q,k from qk; v from tgt)
    gemm_tf32_kernel<<<dim3(4, MT), 256>>>(qk, DM, w_in, DM, in_b, qkv, 768, NQ, 0, nullptr);
    gemm_tf32_kernel<<<dim3(2, MT), 256>>>(tgt, DM, w_in + 512 * DM, DM, in_b + 512, qkv + 512, 768, NQ, 0, nullptr);

    // fused self-attention (scores + softmax + attn@V)
    attn_fused_kernel<<<dim3((LQ + QT - 1) / QT, BB * NH), 256>>>(qkv, sa);

    gemm_tf32_kernel<<<dim3(2, MT), 256>>>(sa, DM, w_out, DM, out_b, tmp, DM, NQ, 0, nullptr);
    add_ln_kernel<<<NQ, 256>>>(tgt, tmp, n2w, n2b, x1, qpos, query);

    // cross-attention inputs
    gemm_tf32_kernel<<<dim3(2, MT), 256>>>(query, DM, w_so, DM, so_b, offs, DM, NQ, 0, nullptr);
    gemm_tf32_kernel<<<dim3(1, MT), 256>>>(query, DM, w_aw, DM, aw_b, awl, 128, NQ, 0, nullptr);
    gemm_tf32_kernel<<<dim3(2, MVT), 256>>>(src, DM, w_vp, DM, vp_b, value, DM, MV, 0, pmask);

    // deformable sampling (writes loc + aw outputs)
    sampling_kernel<<<(NQ * NH * 32 + 255) / 256, 256>>>(refp, offs, awl, value, samp,
                                                         out + 614400, out + 1228800);

    gemm_tf32_kernel<<<dim3(2, MT), 256>>>(samp, DM, w_op, DM, op_b, tmp, DM, NQ, 0, nullptr);
    add_ln_kernel<<<NQ, 256>>>(x1, tmp, n1w, n1b, x2, nullptr, nullptr);

    // FFN
    gemm_tf32_kernel<<<dim3(8, MT), 256>>>(x2, DM, w_l1, DM, l1_b, ffh, DFF, NQ, 1, nullptr);
    gemm_tf32_kernel<<<dim3(2, MT), 256>>>(ffh, DFF, w_l2, DFF, l2_b, ffn, DM, NQ, 0, nullptr);
    add_ln_kernel<<<NQ, 256>>>(x2, ffn, n3w, n3b, out, nullptr, nullptr);
}

// round 13
// speedup vs baseline: 2.2356x; 1.0545x over previous
#include <cuda_runtime.h>
#include <cstdint>
#include <math.h>

// ---------------- problem constants (fixed by reference_code) ----------------
#define BB   8
#define LQ   300
#define DM   256
#define NH   8
#define HD   32
#define NL   4
#define NP   4
#define DFF  1024
#define LV   20197
#define NQ   (BB*LQ)          // 2400
#define MV   (BB*LV)          // 161576

// level constants
__device__ __constant__ int   c_H[NL]  = {100, 50, 25, 13};
__device__ __constant__ int   c_W[NL]  = {152, 76, 38, 19};
__device__ __constant__ int   c_S0[NL] = {0, 15200, 19000, 19950};

// weight-rounding segment table: in,out,so,aw,vp,op,l1,l2
__device__ __constant__ int c_wsz[8]  = {196608, 65536, 65536, 32768, 65536, 65536, 262144, 262144};
__device__ __constant__ int c_woff[8] = {0, 196608, 262144, 327680, 360448, 425984, 491520, 753664};

// ---------------- scratch (device globals; no allocations allowed) ----------
__device__ float g_qk   [NQ*DM];
__device__ float g_qkv  [NQ*3*DM];
__device__ float g_sa   [NQ*DM];
__device__ float g_tmp  [NQ*DM];
__device__ float g_x1   [NQ*DM];
__device__ float g_query[NQ*DM];
__device__ float g_oa   [NQ*384];                 // merged offsets(256) + aw logits(128)
__device__ float g_value[(size_t)MV*DM];          // 165 MB
__device__ float g_samp [NQ*DM];
__device__ float g_x2   [NQ*DM];
__device__ float g_ffh  [NQ*DFF];
__device__ float g_ffn  [NQ*DM];
__device__ float g_wr   [1015808];                // tf32-rounded weights
__device__ float g_soab [384];                    // concat so_b | aw_b

// ---------------- elementwise add ----------------
__global__ void add2_kernel(const float* __restrict__ a, const float* __restrict__ b,
                            float* __restrict__ o, int n) {
    int i = blockIdx.x * blockDim.x + threadIdx.x;
    if (i < n) o[i] = a[i] + b[i];
}

// ---------------- tf32 helpers ----------------
__device__ __forceinline__ uint32_t f2tf32(float f) {
    uint32_t r;
    asm("cvt.rna.tf32.f32 %0, %1;" : "=r"(r) : "f"(f));
    return r;
}

__device__ __forceinline__ void mma_tf32(float c[4],
                                         uint32_t a0, uint32_t a1, uint32_t a2, uint32_t a3,
                                         uint32_t b0, uint32_t b1) {
    asm volatile(
        "mma.sync.aligned.m16n8k8.row.col.f32.tf32.tf32.f32 "
        "{%0,%1,%2,%3}, {%4,%5,%6,%7}, {%8,%9}, {%0,%1,%2,%3};"
        : "+f"(c[0]), "+f"(c[1]), "+f"(c[2]), "+f"(c[3])
        : "r"(a0), "r"(a1), "r"(a2), "r"(a3), "r"(b0), "r"(b1));
}

// ---------------- cp.async helpers ----------------
__device__ __forceinline__ void cp16(uint32_t dst, const void* src, int sz) {
    asm volatile("cp.async.cg.shared.global [%0], [%1], 16, %2;" :: "r"(dst), "l"(src), "r"(sz));
}
__device__ __forceinline__ void cp_commit() { asm volatile("cp.async.commit_group;"); }

// ---------------- round weights to tf32 (rna) once per launch --------------
__global__ void round_w_kernel(const float* __restrict__ p0, const float* __restrict__ p1,
                               const float* __restrict__ p2, const float* __restrict__ p3,
                               const float* __restrict__ p4, const float* __restrict__ p5,
                               const float* __restrict__ p6, const float* __restrict__ p7,
                               float* __restrict__ out)
{
    int m = blockIdx.y;
    int i4 = (blockIdx.x * 256 + threadIdx.x) * 4;
    if (i4 >= c_wsz[m]) return;
    const float* src;
    switch (m) {
        case 0: src = p0; break; case 1: src = p1; break;
        case 2: src = p2; break; case 3: src = p3; break;
        case 4: src = p4; break; case 5: src = p5; break;
        case 6: src = p6; break; default: src = p7; break;
    }
    float4 v = *reinterpret_cast<const float4*>(src + i4);
    v.x = __uint_as_float(f2tf32(v.x));
    v.y = __uint_as_float(f2tf32(v.y));
    v.z = __uint_as_float(f2tf32(v.z));
    v.w = __uint_as_float(f2tf32(v.w));
    *reinterpret_cast<float4*>(out + c_woff[m] + i4) = v;
}

// concat so_b(256) | aw_b(128) into g_soab
__global__ void concat_bias_kernel(const float* __restrict__ so_b,
                                   const float* __restrict__ aw_b,
                                   float* __restrict__ o) {
    int i = threadIdx.x + blockIdx.x * 128;
    if (i < 256) o[i] = so_b[i];
    else if (i < 384) o[i] = aw_b[i - 256];
}

// ---------------- tf32 tensor-core GEMM, 4-stage cp.async pipeline ---------
// C[M,N] = A[M,K] @ W[N,K]^T + bias. BM=128 BN=128 BK=16, 256 threads,
// 8 warps 2x4, warp tile 64x32. Dynamic smem: 4 stages x (A 2560 + B 2560) words.
// A fed as raw fp32 bits (hw tf32 truncation); W must be pre-rounded (rna).
#define GP 20
#define NST 4
#define STW 5120                       // words per stage (A then B)
#define GEMM_SMEM (NST * STW * 4)      // 81920 bytes

__global__ __launch_bounds__(256) void gemm_tf32_kernel(
    const float* __restrict__ A, int lda,
    const float* __restrict__ W, int K,
    const float* __restrict__ bias,
    float* __restrict__ C, int ldc,
    int M, int relu,
    const unsigned char* __restrict__ rowmask)
{
    extern __shared__ uint32_t smem[];

    const int bm = blockIdx.y * 128;
    const int bn = blockIdx.x * 128;
    const int tid  = threadIdx.x;
    const int warp = tid >> 5;
    const int lane = tid & 31;
    const int wm = (warp & 1) * 64;
    const int wn = (warp >> 1) * 32;
    const int grp = lane >> 2;
    const int tig = lane & 3;

    const int mf  = tid >> 2;
    const int kqf = tid & 3;
    const uint32_t sBase = (uint32_t)__cvta_generic_to_shared(smem);
    const uint32_t stageBytes = STW * 4;

    const float* aP0 = A + (size_t)(bm + mf)      * lda + kqf * 4;
    const float* aP1 = A + (size_t)(bm + mf + 64) * lda + kqf * 4;
    const int pr0 = (bm + mf      < M) ? 16 : 0;
    const int pr1 = (bm + mf + 64 < M) ? 16 : 0;
    const float* bP0 = W + (size_t)(bn + mf)      * K + kqf * 4;
    const float* bP1 = W + (size_t)(bn + mf + 64) * K + kqf * 4;
    const uint32_t soA0 = sBase + (mf * GP + kqf * 4) * 4;
    const uint32_t soA1 = sBase + ((mf + 64) * GP + kqf * 4) * 4;
    const uint32_t soB0 = sBase + 2560 * 4 + (mf * GP + kqf * 4) * 4;
    const uint32_t soB1 = sBase + 2560 * 4 + ((mf + 64) * GP + kqf * 4) * 4;

    float acc[4][4][4];
#pragma unroll
    for (int i = 0; i < 4; i++)
#pragma unroll
        for (int j = 0; j < 4; j++)
#pragma unroll
            for (int c = 0; c < 4; c++) acc[i][j][c] = 0.f;

    const int niter = K >> 4;

    // prologue: issue stages 0..NST-2 (always commit -> deterministic group count)
#pragma unroll
    for (int s = 0; s < NST - 1; s++) {
        if (s < niter) {
            const int k1 = s << 4;
            const uint32_t off = s * stageBytes;
            cp16(soA0 + off, aP0 + k1, pr0);
            cp16(soA1 + off, aP1 + k1, pr1);
            cp16(soB0 + off, bP0 + k1, 16);
            cp16(soB1 + off, bP1 + k1, 16);
        }
        cp_commit();
    }

    for (int i = 0; i < niter; i++) {
        asm volatile("cp.async.wait_group 2;");
        __syncthreads();
        {
            const int pf = i + NST - 1;
            if (pf < niter) {
                const int k1 = pf << 4;
                const uint32_t off = (pf & (NST - 1)) * stageBytes;
                cp16(soA0 + off, aP0 + k1, pr0);
                cp16(soA1 + off, aP1 + k1, pr1);
                cp16(soB0 + off, bP0 + k1, 16);
                cp16(soB1 + off, bP1 + k1, 16);
            }
            cp_commit();
        }
        const uint32_t* cA = smem + (i & (NST - 1)) * STW;
        const uint32_t* cB = cA + 2560;
#pragma unroll
        for (int ks = 0; ks < 16; ks += 8) {
            uint32_t b[4][2];
#pragma unroll
            for (int nt = 0; nt < 4; nt++) {
                int col = wn + nt * 8 + grp;
                b[nt][0] = cB[col * GP + ks + tig];
                b[nt][1] = cB[col * GP + ks + tig + 4];
            }
#pragma unroll
            for (int mt = 0; mt < 4; mt++) {
                int row = wm + mt * 16 + grp;
                uint32_t a0 = cA[row * GP + ks + tig];
                uint32_t a1 = cA[(row + 8) * GP + ks + tig];
                uint32_t a2 = cA[row * GP + ks + tig + 4];
                uint32_t a3 = cA[(row + 8) * GP + ks + tig + 4];
#pragma unroll
                for (int nt = 0; nt < 4; nt++)
                    mma_tf32(acc[mt][nt], a0, a1, a2, a3, b[nt][0], b[nt][1]);
            }
        }
    }

    // epilogue
#pragma unroll
    for (int mt = 0; mt < 4; mt++) {
#pragma unroll
        for (int half = 0; half < 2; half++) {
            int gm = bm + wm + mt * 16 + grp + half * 8;
            if (gm >= M) continue;
            bool mz = (rowmask != nullptr) && rowmask[gm];
#pragma unroll
            for (int nt = 0; nt < 4; nt++) {
                int gn = bn + wn + nt * 8 + 2 * tig;
                float v0 = acc[mt][nt][half * 2 + 0] + bias[gn];
                float v1 = acc[mt][nt][half * 2 + 1] + bias[gn + 1];
                if (relu) { v0 = fmaxf(v0, 0.f); v1 = fmaxf(v1, 0.f); }
                if (mz) { v0 = 0.f; v1 = 0.f; }
                float2* o = reinterpret_cast<float2*>(C + (size_t)gm * ldc + gn);
                *o = make_float2(v0, v1);
            }
        }
    }
}

// ---------------- fused self-attention: scores + softmax + attn@V ----------
#define QT 24
#define KVP 36

__global__ __launch_bounds__(256) void attn_fused_kernel(
    const float* __restrict__ qkv, float* __restrict__ sa)
{
    __shared__ float sQ[QT * KVP];
    __shared__ float sKV[64 * KVP];
    __shared__ float sS[QT * 300];

    const int tid = threadIdx.x;
    const int bh = blockIdx.y;
    const int b = bh >> 3, h = bh & 7;
    const int q0 = blockIdx.x * QT;

    for (int idx = tid; idx < QT * 32; idx += 256) {
        int r = idx >> 5, d = idx & 31;
        float v = 0.f;
        if (q0 + r < LQ) v = qkv[(size_t)(b * LQ + q0 + r) * 768 + h * 32 + d];
        sQ[r * KVP + d] = v;
    }

    const int kk = tid & 63;
    const int qb1 = tid >> 6;
    for (int k0 = 0; k0 < LQ; k0 += 64) {
        int kn = min(64, LQ - k0);
        __syncthreads();
        for (int idx = tid; idx < 64 * 32; idx += 256) {
            int r = idx >> 5, d = idx & 31;
            if (r < kn)
                sKV[r * KVP + d] = qkv[(size_t)(b * LQ + k0 + r) * 768 + 256 + h * 32 + d];
        }
        __syncthreads();
        if (kk < kn) {
#pragma unroll
            for (int i = 0; i < QT / 4; i++) {
                int q = qb1 + 4 * i;
                float dot = 0.f;
#pragma unroll
                for (int dq = 0; dq < 8; dq++) {
                    float4 qv = *reinterpret_cast<const float4*>(&sQ[q * KVP + dq * 4]);
                    float4 kv = *reinterpret_cast<const float4*>(&sKV[kk * KVP + dq * 4]);
                    dot = fmaf(qv.x, kv.x, dot);
                    dot = fmaf(qv.y, kv.y, dot);
                    dot = fmaf(qv.z, kv.z, dot);
                    dot = fmaf(qv.w, kv.w, dot);
                }
                sS[q * 300 + k0 + kk] = dot * 0.1767766952966369f;
            }
        }
    }
    __syncthreads();

    {
        int warp = tid >> 5, lane = tid & 31;
#pragma unroll
        for (int i = 0; i < 3; i++) {
            float* row = &sS[(warp + 8 * i) * 300];
            float mx = -1e30f;
            for (int j = lane; j < 300; j += 32) mx = fmaxf(mx, row[j]);
#pragma unroll
            for (int o = 16; o; o >>= 1) mx = fmaxf(mx, __shfl_xor_sync(0xffffffffu, mx, o));
            float s = 0.f;
            for (int j = lane; j < 300; j += 32) { float e = __expf(row[j] - mx); row[j] = e; s += e; }
#pragma unroll
            for (int o = 16; o; o >>= 1) s += __shfl_xor_sync(0xffffffffu, s, o);
            float inv = 1.f / s;
            for (int j = lane; j < 300; j += 32) row[j] *= inv;
        }
    }

    const int d2 = (tid & 15) * 2;
    const int qb2 = tid >> 4;
    float acc0 = 0.f, acc1 = 0.f, acc2 = 0.f, acc3 = 0.f;
    for (int k0 = 0; k0 < LQ; k0 += 64) {
        int kn = min(64, LQ - k0);
        __syncthreads();
        for (int idx = tid; idx < 64 * 32; idx += 256) {
            int r = idx >> 5, d = idx & 31;
            if (r < kn)
                sKV[r * KVP + d] = qkv[(size_t)(b * LQ + k0 + r) * 768 + 512 + h * 32 + d];
        }
        __syncthreads();
        for (int j = 0; j < kn; j++) {
            float2 vv = *reinterpret_cast<const float2*>(&sKV[j * KVP + d2]);
            float p0 = sS[qb2 * 300 + k0 + j];
            acc0 = fmaf(p0, vv.x, acc0);
            acc1 = fmaf(p0, vv.y, acc1);
            if (qb2 + 16 < QT) {
                float p1 = sS[(qb2 + 16) * 300 + k0 + j];
                acc2 = fmaf(p1, vv.x, acc2);
                acc3 = fmaf(p1, vv.y, acc3);
            }
        }
    }
    if (q0 + qb2 < LQ) {
        float2* o = reinterpret_cast<float2*>(sa + (size_t)(b * LQ + q0 + qb2) * DM + h * 32 + d2);
        *o = make_float2(acc0, acc1);
    }
    if (qb2 + 16 < QT && q0 + qb2 + 16 < LQ) {
        float2* o = reinterpret_cast<float2*>(sa + (size_t)(b * LQ + q0 + qb2 + 16) * DM + h * 32 + d2);
        *o = make_float2(acc2, acc3);
    }
}

// ---------------- residual + layernorm (+ optional query out) --------------
__global__ void add_ln_kernel(const float* __restrict__ A, const float* __restrict__ R,
                              const float* __restrict__ w, const float* __restrict__ bias,
                              float* __restrict__ out,
                              const float* __restrict__ qpos, float* __restrict__ qout)
{
    __shared__ float sm[8];
    int row = blockIdx.x, t = threadIdx.x;
    size_t base = (size_t)row * DM + t;
    float v = A[base] + R[base];

    float s = v;
#pragma unroll
    for (int o = 16; o; o >>= 1) s += __shfl_xor_sync(0xffffffffu, s, o);
    if ((t & 31) == 0) sm[t >> 5] = s;
    __syncthreads();
    float mean = (sm[0]+sm[1]+sm[2]+sm[3]+sm[4]+sm[5]+sm[6]+sm[7]) * (1.f/DM);
    __syncthreads();

    float d = v - mean;
    float s2 = d * d;
#pragma unroll
    for (int o = 16; o; o >>= 1) s2 += __shfl_xor_sync(0xffffffffu, s2, o);
    if ((t & 31) == 0) sm[t >> 5] = s2;
    __syncthreads();
    float var = (sm[0]+sm[1]+sm[2]+sm[3]+sm[4]+sm[5]+sm[6]+sm[7]) * (1.f/DM);

    float y = d * rsqrtf(var + 1e-5f) * w[t] + bias[t];
    out[base] = y;
    if (qout) qout[base] = y + qpos[base];
}

// ---------------- deformable sampling: one warp per (b,q,h) ----------------
// reads merged oa buffer: offsets at [bq*384 + 0..255], aw logits at [bq*384+256..383]
__global__ void sampling_kernel(const float* __restrict__ refp, const float* __restrict__ oa,
                                const float* __restrict__ value,
                                float* __restrict__ samp,
                                float* __restrict__ out_loc, float* __restrict__ out_aw)
{
    int warp = (blockIdx.x * blockDim.x + threadIdx.x) >> 5;
    int lane = threadIdx.x & 31;
    if (warp >= NQ * NH) return;
    int h = warp & 7;
    int bq = warp >> 3;
    int b = bq / LQ;

    float logit = (lane < 16) ? oa[(size_t)bq * 384 + 256 + h * 16 + lane] : -1e30f;
    float mx = logit;
#pragma unroll
    for (int o = 8; o; o >>= 1) mx = fmaxf(mx, __shfl_xor_sync(0xffffffffu, mx, o));
    float e = (lane < 16) ? __expf(logit - mx) : 0.f;
    float ssum = e;
#pragma unroll
    for (int o = 8; o; o >>= 1) ssum += __shfl_xor_sync(0xffffffffu, ssum, o);
    float myaw = (lane < 16) ? (e / ssum) : 0.f;
    if (lane < 16) out_aw[(size_t)(bq * NH + h) * 16 + lane] = myaw;

    const float* vbase = value + (size_t)b * LV * DM + h * 32 + lane;
    float acc = 0.f;

#pragma unroll
    for (int k = 0; k < 16; k++) {
        int l = k >> 2;
        float Wf = (float)c_W[l], Hf = (float)c_H[l];
        int   Wi = c_W[l], Hi = c_H[l], s0 = c_S0[l];

        float rx = refp[(size_t)(bq * NL + l) * 2 + 0];
        float ry = refp[(size_t)(bq * NL + l) * 2 + 1];
        float ox = oa[(size_t)bq * 384 + ((h * NL + l) * NP + (k & 3)) * 2 + 0];
        float oy = oa[(size_t)bq * 384 + ((h * NL + l) * NP + (k & 3)) * 2 + 1];
        float locx = rx + ox / Wf;
        float locy = ry + oy / Hf;
        if (lane == 0) {
            size_t lo = ((size_t)(bq * NH + h) * 16 + k) * 2;
            out_loc[lo + 0] = locx;
            out_loc[lo + 1] = locy;
        }
        float awk = __shfl_sync(0xffffffffu, myaw, k);

        float x = locx * Wf - 0.5f;
        float y = locy * Hf - 0.5f;
        float x0f = floorf(x), y0f = floorf(y);
        float lx = x - x0f, ly = y - y0f;
        int x0 = (int)x0f, y0 = (int)y0f;

        float sv = 0.f;
#pragma unroll
        for (int c = 0; c < 4; c++) {
            int ix = x0 + (c & 1);
            int iy = y0 + (c >> 1);
            float wgt = ((c & 1) ? lx : 1.f - lx) * ((c >> 1) ? ly : 1.f - ly);
            bool valid = (ix >= 0) && (ix < Wi) && (iy >= 0) && (iy < Hi);
            int cix = min(max(ix, 0), Wi - 1);
            int ciy = min(max(iy, 0), Hi - 1);
            float g = vbase[(size_t)(s0 + ciy * Wi + cix) * DM];
            sv = fmaf(g, valid ? wgt : 0.f, sv);
        }
        acc = fmaf(awk, sv, acc);
    }
    samp[(size_t)bq * DM + h * 32 + lane] = acc;
}

// ---------------- launch ----------------
extern "C" void kernel_launch(void* const* d_in, const int* in_sizes, int n_in,
                              void* d_out, int out_size)
{
    const float* tgt  = (const float*)d_in[0];
    const float* qpos = (const float*)d_in[1];
    const float* refp = (const float*)d_in[2];
    const float* src  = (const float*)d_in[3];
    const float* in_w = (const float*)d_in[4];
    const float* in_b = (const float*)d_in[5];
    const float* out_w= (const float*)d_in[6];
    const float* out_b= (const float*)d_in[7];
    const float* so_w = (const float*)d_in[8];
    const float* so_b = (const float*)d_in[9];
    const float* aw_w = (const float*)d_in[10];
    const float* aw_b = (const float*)d_in[11];
    const float* vp_w = (const float*)d_in[12];
    const float* vp_b = (const float*)d_in[13];
    const float* op_w = (const float*)d_in[14];
    const float* op_b = (const float*)d_in[15];
    const float* l1_w = (const float*)d_in[16];
    const float* l1_b = (const float*)d_in[17];
    const float* l2_w = (const float*)d_in[18];
    const float* l2_b = (const float*)d_in[19];
    const float* n1w  = (const float*)d_in[20];
    const float* n1b  = (const float*)d_in[21];
    const float* n2w  = (const float*)d_in[22];
    const float* n2b  = (const float*)d_in[23];
    const float* n3w  = (const float*)d_in[24];
    const float* n3b  = (const float*)d_in[25];
    const unsigned char* pmask = (const unsigned char*)d_in[28];
    float* out = (float*)d_out;

    // idempotent, host-side; no static guard (harness forbids static state)
    cudaFuncSetAttribute(gemm_tf32_kernel,
                         cudaFuncAttributeMaxDynamicSharedMemorySize, GEMM_SMEM);

    float *qk, *qkv, *sa, *tmp, *x1, *query, *oa, *value, *samp, *x2, *ffh, *ffn, *wr, *soab;
    cudaGetSymbolAddress((void**)&qk,    g_qk);
    cudaGetSymbolAddress((void**)&qkv,   g_qkv);
    cudaGetSymbolAddress((void**)&sa,    g_sa);
    cudaGetSymbolAddress((void**)&tmp,   g_tmp);
    cudaGetSymbolAddress((void**)&x1,    g_x1);
    cudaGetSymbolAddress((void**)&query, g_query);
    cudaGetSymbolAddress((void**)&oa,    g_oa);
    cudaGetSymbolAddress((void**)&value, g_value);
    cudaGetSymbolAddress((void**)&samp,  g_samp);
    cudaGetSymbolAddress((void**)&x2,    g_x2);
    cudaGetSymbolAddress((void**)&ffh,   g_ffh);
    cudaGetSymbolAddress((void**)&ffn,   g_ffn);
    cudaGetSymbolAddress((void**)&wr,    g_wr);
    cudaGetSymbolAddress((void**)&soab,  g_soab);

    const int MT  = (NQ + 127) / 128;     // 19
    const int MVT = (MV + 127) / 128;     // 1263

    // pre-round all weight matrices to tf32 (rna) + concat so/aw bias
    round_w_kernel<<<dim3(256, 8), 256>>>(in_w, out_w, so_w, aw_w, vp_w, op_w, l1_w, l2_w, wr);
    concat_bias_kernel<<<3, 128>>>(so_b, aw_b, soab);

    const float* w_in  = wr + 0;
    const float* w_out = wr + 196608;
    const float* w_soaw= wr + 262144;     // so(256 rows) | aw(128 rows), adjacent
    const float* w_vp  = wr + 360448;
    const float* w_op  = wr + 425984;
    const float* w_l1  = wr + 491520;
    const float* w_l2  = wr + 753664;

    // qk = tgt + query_pos
    add2_kernel<<<(NQ * DM + 255) / 256, 256>>>(tgt, qpos, qk, NQ * DM);

    // QKV projection (q,k from qk; v from tgt)
    gemm_tf32_kernel<<<dim3(4, MT), 256, GEMM_SMEM>>>(qk, DM, w_in, DM, in_b, qkv, 768, NQ, 0, nullptr);
    gemm_tf32_kernel<<<dim3(2, MT), 256, GEMM_SMEM>>>(tgt, DM, w_in + 512 * DM, DM, in_b + 512, qkv + 512, 768, NQ, 0, nullptr);

    // fused self-attention (scores + softmax + attn@V)
    attn_fused_kernel<<<dim3((LQ + QT - 1) / QT, BB * NH), 256>>>(qkv, sa);

    gemm_tf32_kernel<<<dim3(2, MT), 256, GEMM_SMEM>>>(sa, DM, w_out, DM, out_b, tmp, DM, NQ, 0, nullptr);
    add_ln_kernel<<<NQ, 256>>>(tgt, tmp, n2w, n2b, x1, qpos, query);

    // cross-attention inputs: merged sampling-offset + attention-weight GEMM (N=384)
    gemm_tf32_kernel<<<dim3(3, MT), 256, GEMM_SMEM>>>(query, DM, w_soaw, DM, soab, oa, 384, NQ, 0, nullptr);
    gemm_tf32_kernel<<<dim3(2, MVT), 256, GEMM_SMEM>>>(src, DM, w_vp, DM, vp_b, value, DM, MV, 0, pmask);

    // deformable sampling (writes loc + aw outputs)
    sampling_kernel<<<(NQ * NH * 32 + 255) / 256, 256>>>(refp, oa, value, samp,
                                                         out + 614400, out + 1228800);

    gemm_tf32_kernel<<<dim3(2, MT), 256, GEMM_SMEM>>>(samp, DM, w_op, DM, op_b, tmp, DM, NQ, 0, nullptr);
    add_ln_kernel<<<NQ, 256>>>(x1, tmp, n1w, n1b, x2, nullptr, nullptr);

    // FFN
    gemm_tf32_kernel<<<dim3(8, MT), 256, GEMM_SMEM>>>(x2, DM, w_l1, DM, l1_b, ffh, DFF, NQ, 1, nullptr);
    gemm_tf32_kernel<<<dim3(2, MT), 256, GEMM_SMEM>>>(ffh, DFF, w_l2, DFF, l2_b, ffn, DM, NQ, 0, nullptr);
    add_ln_kernel<<<NQ, 256>>>(x2, ffn, n3w, n3b, out, nullptr, nullptr);
}